// round 7
// baseline (speedup 1.0000x reference)
#include <cuda_runtime.h>
#include <cuda_fp16.h>
#include <mma.h>
#include <cstdint>
#include <math_constants.h>
#include <math.h>

using namespace nvcuda;

// ---------------- problem constants ----------------
#define DD 6
#define HH 128
#define WW 128
#define CC 180
#define NHD 6
#define HDIM 30
#define NWIN 768
#define NTOK 128
#define M_ROWS 98304
#define C3 540
#define C2 360
#define HID 360
#define QKV_STR 576          // padded qkv row stride
#define HID_STR 384          // padded hidden row stride
#define ATT_SCALE 0.18257418583505536f

// ---------------- scratch (device globals; allocs are banned) ----------------
__device__ float g_xw[M_ROWS * CC];
__device__ float g_qkvS[M_ROWS * QKV_STR];
__device__ float g_qkvM[M_ROWS * QKV_STR];
__device__ float g_xo[M_ROWS * C2];
__device__ float g_y[M_ROWS * CC];
__device__ float g_h2[M_ROWS * CC];
__device__ float g_hid1[M_ROWS * HID_STR];
__device__ float g_bias6[NHD * NTOK * NTOK];
// fp16 transposed+padded weights: [Npad, Kpad]
__device__ __half g_wT_qs[576 * 192];
__device__ __half g_wT_qm[576 * 192];
__device__ __half g_wT_pr[192 * 384];
__device__ __half g_wT_f11[384 * 192];
__device__ __half g_wT_f12[384 * 192];
__device__ __half g_wT_f2[192 * 384];

template <int ID> __device__ __forceinline__ float* fbuf() {
    if (ID == 0) return g_xw;
    if (ID == 1) return g_qkvS;
    if (ID == 2) return g_qkvM;
    if (ID == 3) return g_xo;
    if (ID == 4) return g_y;
    if (ID == 5) return g_h2;
    return g_hid1;
}
template <int ID> __device__ __forceinline__ __half* wbuf() {
    if (ID == 0) return g_wT_qs;
    if (ID == 1) return g_wT_qm;
    if (ID == 2) return g_wT_pr;
    if (ID == 3) return g_wT_f11;
    if (ID == 4) return g_wT_f12;
    return g_wT_f2;
}

__device__ __forceinline__ int row_to_img(int r) {
    int win = r >> 7, n = r & 127;
    int dwin = win >> 8, rem = win & 255;
    int hwin = rem >> 4, wwin = rem & 15;
    int nd = n >> 6, nh = (n >> 3) & 7, nw = n & 7;
    int sd = dwin * 2 + nd + 1; if (sd >= 6) sd -= 6;
    int sh = (hwin * 8 + nh + 4) & 127;
    int sw = (wwin * 8 + nw + 4) & 127;
    return (sd * 128 + sh) * 128 + sw;
}

// ---------------- weight prep (2 launches so ncu -s 5 lands on a GEMM) ----------------
__device__ __forceinline__ void prep_one(const float* w, __half* wt, int idx,
                                         int K, int N, int Kpad, int Npad) {
    int n = idx / Kpad, k = idx % Kpad;
    wt[idx] = (n < N && k < K) ? __float2half(w[(long)k * N + n]) : __float2half(0.f);
}
__global__ void prep_qkv_kernel(const float* __restrict__ wqs, const float* __restrict__ wqm) {
    int idx = blockIdx.x * blockDim.x + threadIdx.x;
    if (idx < 576 * 192) prep_one(wqs, g_wT_qs, idx, CC, C3, 192, 576);
    else if (idx < 2 * 576 * 192) prep_one(wqm, g_wT_qm, idx - 576 * 192, CC, C3, 192, 576);
}
__global__ void prep_rest_kernel(const float* __restrict__ wproj, const float* __restrict__ w11,
                                 const float* __restrict__ w12, const float* __restrict__ w2) {
    int idx = blockIdx.x * blockDim.x + threadIdx.x;
    const int S = 192 * 384;
    if (idx < S) prep_one(wproj, g_wT_pr, idx, C2, CC, 384, 192);
    else if (idx < 2 * S) prep_one(w11, g_wT_f11, idx - S, CC, HID, 192, 384);
    else if (idx < 3 * S) prep_one(w12, g_wT_f12, idx - 2 * S, CC, HID, 192, 384);
    else if (idx < 4 * S) prep_one(w2, g_wT_f2, idx - 3 * S, HID, CC, 384, 192);
}

// ---------------- rel-pos bias gather ----------------
__global__ void bias_kernel(const float* __restrict__ rpb, const int* __restrict__ rpi) {
    int idx = blockIdx.x * blockDim.x + threadIdx.x;
    if (idx >= NHD * NTOK * NTOK) return;
    int h = idx / (NTOK * NTOK), ij = idx % (NTOK * NTOK);
    g_bias6[idx] = rpb[rpi[ij] * NHD + h];
}

// ---------------- LayerNorm ----------------
template <int MODE>
__global__ __launch_bounds__(256) void ln_kernel(const float* __restrict__ in,
                                                 const float* __restrict__ gg,
                                                 const float* __restrict__ bb) {
    const float* src_buf = (MODE == 0) ? in : fbuf<4>();
    float* dst_buf = (MODE == 0) ? fbuf<0>() : fbuf<5>();
    int gw = (blockIdx.x * blockDim.x + threadIdx.x) >> 5;
    int lane = threadIdx.x & 31;
    if (gw >= M_ROWS) return;
    int srcrow = (MODE == 0) ? row_to_img(gw) : gw;
    const float* rowp = src_buf + (long)srcrow * CC;
    float vals[6];
    float s = 0.f, ss = 0.f;
    int cnt = 0;
    for (int c = lane; c < CC; c += 32) { float v = rowp[c]; vals[cnt++] = v; s += v; ss += v * v; }
#pragma unroll
    for (int o = 16; o > 0; o >>= 1) {
        s  += __shfl_xor_sync(0xffffffffu, s, o);
        ss += __shfl_xor_sync(0xffffffffu, ss, o);
    }
    float mean = s * (1.f / CC);
    float var = ss * (1.f / CC) - mean * mean;
    float rstd = rsqrtf(var + 1e-5f);
    float* orow = dst_buf + (long)gw * CC;
    cnt = 0;
    for (int c = lane; c < CC; c += 32)
        orow[c] = (vals[cnt++] - mean) * rstd * gg[c] + bb[c];
}

// ---------------- wmma fp16 GEMM ----------------
// MODE 0: C = A@W^T + bias, ALL tiles full (padded Nstride) -> direct global store
// MODE 1: y[img] = x[img] + (A@W^T + bias)   (proj scatter)
// MODE 2: out[r] = g_y[r] + (A@W^T + bias)   (fc2 residual)
// MODE 3: hid1[r, 0..Nstride) = gelu(A@W1^T + b1) * (A@W2^T + b2)
template <int KPAD, int ADD_PB, int MODE, int SRC, int DST, int WID, int WID2>
__global__ __launch_bounds__(256) void gemm_wmma(const float* __restrict__ bias,
                                                 const float* __restrict__ bias2,
                                                 float* __restrict__ CoutExt,
                                                 const float* __restrict__ extA,
                                                 const float* __restrict__ pb,
                                                 int Kreal, int Astride, int Nreal,
                                                 int Nstride, int Ntiles) {
    const float* A = fbuf<SRC>();
    const __half* BT1 = wbuf<WID>();
    const __half* BT2 = wbuf<WID2>();
    float* Cout = (DST >= 0) ? fbuf<(DST >= 0 ? DST : 0)>() : CoutExt;
    const float* addsrc = (MODE == 1) ? extA : fbuf<4>();
    constexpr int NPASS = (MODE == 3) ? 2 : 1;

    constexpr int LDA = KPAD + 8;
    constexpr int LDC = 68;
    extern __shared__ __align__(16) char smem[];
    __half* As = (__half*)smem;                  // [128][LDA]
    __half* Bs = As + 128 * LDA;                 // [64][LDA]
    float*  Cs = (float*)(Bs + 64 * LDA);        // [128][LDC] (MODE 0: only 16 rows used as bias tile)
    float*  Cs2 = (MODE == 3) ? (Cs + 128 * LDC) : Cs;
    float*  biasS = (MODE == 3) ? (Cs2 + 128 * LDC) : Cs;   // MODE 1/2 alias onto Cs

    int tid = threadIdx.x, wid = tid >> 5;
    int m0 = blockIdx.x * 128;

    // ---- stage A tile [128][KPAD] fp16 ----
    constexpr int KF4 = KPAD / 4;
    int kreal4 = Kreal >> 2;
    for (int idx = tid; idx < 128 * KF4; idx += 256) {
        int row = idx / KF4, c4 = idx % KF4;
        uint2 val = make_uint2(0u, 0u);
        if (c4 < kreal4) {
            float4 a = *(const float4*)(A + (long)(m0 + row) * Astride + c4 * 4);
            if (ADD_PB) {
                float4 p = *(const float4*)(pb + ((m0 + row) & 63) * CC + c4 * 4);
                a.x += p.x; a.y += p.y; a.z += p.z; a.w += p.w;
            }
            __half2 h0 = __floats2half2_rn(a.x, a.y);
            __half2 h1 = __floats2half2_rn(a.z, a.w);
            val.x = *(uint32_t*)&h0;
            val.y = *(uint32_t*)&h1;
        }
        *(uint2*)(As + row * LDA + c4 * 4) = val;
    }

    int wm = (wid & 3) * 32;
    int wn = (wid >> 2) * 32;

    for (int t = 0; t < Ntiles; t++) {
        int n0 = t * 64;

#pragma unroll
        for (int pass = 0; pass < NPASS; pass++) {
            const __half* Bp = (pass == 0) ? BT1 : BT2;
            const float* bp = (pass == 0) ? bias : bias2;
            float* Cdst = (pass == 0) ? Cs : Cs2;

            for (int idx = tid; idx < 16 * 64; idx += 256) {
                int row = idx >> 6, c = idx & 63;
                biasS[row * LDC + c] = (n0 + c < Nreal) ? bp[n0 + c] : 0.f;
            }
            constexpr int BU4 = KPAD / 8;
            for (int idx = tid; idx < 64 * BU4; idx += 256) {
                int n = idx / BU4, c = idx % BU4;
                uint4 v = *(const uint4*)(Bp + (long)(n0 + n) * KPAD + c * 8);
                *(uint4*)(Bs + n * LDA + c * 8) = v;
            }
            __syncthreads();

            wmma::fragment<wmma::accumulator, 16, 16, 16, float> acc[2][2];
#pragma unroll
            for (int i = 0; i < 2; i++)
#pragma unroll
                for (int j = 0; j < 2; j++)
                    wmma::load_matrix_sync(acc[i][j], biasS + wn + j * 16, LDC, wmma::mem_row_major);

#pragma unroll
            for (int k = 0; k < KPAD; k += 16) {
                wmma::fragment<wmma::matrix_a, 16, 16, 16, __half, wmma::row_major> af[2];
                wmma::fragment<wmma::matrix_b, 16, 16, 16, __half, wmma::col_major> bf[2];
#pragma unroll
                for (int i = 0; i < 2; i++)
                    wmma::load_matrix_sync(af[i], As + (wm + i * 16) * LDA + k, LDA);
#pragma unroll
                for (int j = 0; j < 2; j++)
                    wmma::load_matrix_sync(bf[j], Bs + (wn + j * 16) * LDA + k, LDA);
#pragma unroll
                for (int i = 0; i < 2; i++)
#pragma unroll
                    for (int j = 0; j < 2; j++)
                        wmma::mma_sync(acc[i][j], af[i], bf[j], acc[i][j]);
            }

            if (MODE == 0) {
#pragma unroll
                for (int i = 0; i < 2; i++)
#pragma unroll
                    for (int j = 0; j < 2; j++)
                        wmma::store_matrix_sync(Cout + (long)(m0 + wm + i * 16) * Nstride + n0 + wn + j * 16,
                                                acc[i][j], Nstride, wmma::mem_row_major);
            } else {
#pragma unroll
                for (int i = 0; i < 2; i++)
#pragma unroll
                    for (int j = 0; j < 2; j++)
                        wmma::store_matrix_sync(Cdst + (wm + i * 16) * LDC + wn + j * 16,
                                                acc[i][j], LDC, wmma::mem_row_major);
            }
            __syncthreads();
        }

        if (MODE != 0) {
            int nlim = (MODE == 3) ? Nstride : Nreal;
            for (int idx = tid; idx < 128 * 16; idx += 256) {
                int row = idx >> 4, c4 = (idx & 15) * 4;
                int n = n0 + c4;
                if (n + 4 <= nlim) {
                    float4 v = *(float4*)(Cs + row * LDC + c4);
                    int r = m0 + row;
                    if (MODE == 1) {
                        int img = row_to_img(r);
                        const float4 xr = *(const float4*)(addsrc + (long)img * CC + n);
                        v.x += xr.x; v.y += xr.y; v.z += xr.z; v.w += xr.w;
                        *(float4*)(Cout + (long)img * CC + n) = v;
                    } else if (MODE == 2) {
                        const float4 yr = *(const float4*)(addsrc + (long)r * CC + n);
                        v.x += yr.x; v.y += yr.y; v.z += yr.z; v.w += yr.w;
                        *(float4*)(Cout + (long)r * CC + n) = v;
                    } else {
                        float4 v2 = *(float4*)(Cs2 + row * LDC + c4);
                        float4 o;
                        o.x = 0.5f * v.x * (1.f + erff(v.x * 0.70710678f)) * v2.x;
                        o.y = 0.5f * v.y * (1.f + erff(v.y * 0.70710678f)) * v2.y;
                        o.z = 0.5f * v.z * (1.f + erff(v.z * 0.70710678f)) * v2.z;
                        o.w = 0.5f * v.w * (1.f + erff(v.w * 0.70710678f)) * v2.w;
                        *(float4*)(Cout + (long)r * Nstride + n) = o;
                    }
                }
            }
            __syncthreads();
        }
    }
}

// ---------------- self attention: 64 threads, 2 queries/thread ----------------
__global__ __launch_bounds__(64) void self_attn_kernel(const float* __restrict__ mask) {
    int h = blockIdx.x, w = blockIdx.y, t = threadIdx.x;
    __shared__ float Ks[128 * 32];
    __shared__ float Vs[128 * 32];
    const float* base = g_qkvS + (long)w * NTOK * QKV_STR;
    // stage K/V rows t and t+64
#pragma unroll
    for (int j = 0; j < 2; j++) {
        int row = t + j * 64;
        const float* rp = base + row * QKV_STR + h * HDIM;
        float* kd = Ks + row * 32;
        float* vd = Vs + row * 32;
#pragma unroll
        for (int d = 0; d < HDIM; d++) { kd[d] = rp[180 + d]; vd[d] = rp[360 + d]; }
        kd[30] = kd[31] = vd[30] = vd[31] = 0.f;
    }
    float q0[32], q1[32];
#pragma unroll
    for (int d = 0; d < 32; d++) { q0[d] = 0.f; q1[d] = 0.f; }
    const float* qr0 = base + t * QKV_STR + h * HDIM;
    const float* qr1 = base + (t + 64) * QKV_STR + h * HDIM;
#pragma unroll
    for (int d = 0; d < HDIM; d++) { q0[d] = qr0[d] * ATT_SCALE; q1[d] = qr1[d] * ATT_SCALE; }
    __syncthreads();
    const float* br0 = g_bias6 + h * (NTOK * NTOK) + t * NTOK;
    const float* br1 = br0 + 64 * NTOK;
    const float* mr0 = mask + (long)w * (NTOK * NTOK) + t * NTOK;
    const float* mr1 = mr0 + 64 * NTOK;
    float acc0[32], acc1[32];
#pragma unroll
    for (int d = 0; d < 32; d++) { acc0[d] = 0.f; acc1[d] = 0.f; }
    float sum0 = 0.f, sum1 = 0.f;
#pragma unroll 2
    for (int m = 0; m < 128; m++) {
        const float4* kp = (const float4*)(Ks + m * 32);
        float d0 = 0.f, d1 = 0.f;
#pragma unroll
        for (int tt = 0; tt < 8; tt++) {
            float4 kv = kp[tt];
            d0 += q0[4 * tt] * kv.x + q0[4 * tt + 1] * kv.y + q0[4 * tt + 2] * kv.z + q0[4 * tt + 3] * kv.w;
            d1 += q1[4 * tt] * kv.x + q1[4 * tt + 1] * kv.y + q1[4 * tt + 2] * kv.z + q1[4 * tt + 3] * kv.w;
        }
        float p0 = __expf(d0 + br0[m] + mr0[m]);
        float p1 = __expf(d1 + br1[m] + mr1[m]);
        sum0 += p0; sum1 += p1;
        const float4* vp = (const float4*)(Vs + m * 32);
#pragma unroll
        for (int tt = 0; tt < 8; tt++) {
            float4 vv = vp[tt];
            acc0[4 * tt] += p0 * vv.x; acc0[4 * tt + 1] += p0 * vv.y;
            acc0[4 * tt + 2] += p0 * vv.z; acc0[4 * tt + 3] += p0 * vv.w;
            acc1[4 * tt] += p1 * vv.x; acc1[4 * tt + 1] += p1 * vv.y;
            acc1[4 * tt + 2] += p1 * vv.z; acc1[4 * tt + 3] += p1 * vv.w;
        }
    }
    float i0 = 1.f / sum0, i1 = 1.f / sum1;
    float* o0 = g_xo + (long)(w * NTOK + t) * C2 + CC + h * HDIM;
    float* o1 = g_xo + (long)(w * NTOK + t + 64) * C2 + CC + h * HDIM;
#pragma unroll
    for (int d = 0; d < HDIM; d++) { o0[d] = acc0[d] * i0; o1[d] = acc1[d] * i1; }
}

// ---------------- mutual attention: 64 threads, 2 queries/thread ----------------
__global__ __launch_bounds__(64) void mut_attn_kernel(const float* __restrict__ mask) {
    int h = blockIdx.x, w = blockIdx.y, t = threadIdx.x;
    int g = t >> 5, r0 = t & 31;           // this thread: queries r0, r0+32 of group g
    __shared__ float Ks[128 * 32];
    __shared__ float Vs[128 * 32];
    const float* base = g_qkvM + (long)w * NTOK * QKV_STR;
#pragma unroll
    for (int j = 0; j < 2; j++) {
        int row = t + j * 64;
        const float* rp = base + row * QKV_STR + h * HDIM;
        float* kd = Ks + row * 32;
        float* vd = Vs + row * 32;
#pragma unroll
        for (int d = 0; d < HDIM; d++) { kd[d] = rp[180 + d]; vd[d] = rp[360 + d]; }
        kd[30] = kd[31] = vd[30] = vd[31] = 0.f;
    }
    // queries from opposite half
    int qt0 = (1 - g) * 64 + r0;
    int qt1 = qt0 + 32;
    float q0[32], q1[32];
#pragma unroll
    for (int d = 0; d < 32; d++) { q0[d] = 0.f; q1[d] = 0.f; }
    const float* qr0 = base + qt0 * QKV_STR + h * HDIM;
    const float* qr1 = base + qt1 * QKV_STR + h * HDIM;
#pragma unroll
    for (int d = 0; d < HDIM; d++) { q0[d] = qr0[d] * ATT_SCALE; q1[d] = qr1[d] * ATT_SCALE; }
    __syncthreads();
    const float* mr0 = mask + (long)w * (NTOK * NTOK) + r0 * NTOK;
    const float* mr1 = mr0 + 32 * NTOK;
    const float* Kg = Ks + g * 64 * 32;
    const float* Vg = Vs + g * 64 * 32;
    float acc0[32], acc1[32];
#pragma unroll
    for (int d = 0; d < 32; d++) { acc0[d] = 0.f; acc1[d] = 0.f; }
    float sum0 = 0.f, sum1 = 0.f;
#pragma unroll 2
    for (int m = 0; m < 64; m++) {
        const float4* kp = (const float4*)(Kg + m * 32);
        float d0 = 0.f, d1 = 0.f;
#pragma unroll
        for (int tt = 0; tt < 8; tt++) {
            float4 kv = kp[tt];
            d0 += q0[4 * tt] * kv.x + q0[4 * tt + 1] * kv.y + q0[4 * tt + 2] * kv.z + q0[4 * tt + 3] * kv.w;
            d1 += q1[4 * tt] * kv.x + q1[4 * tt + 1] * kv.y + q1[4 * tt + 2] * kv.z + q1[4 * tt + 3] * kv.w;
        }
        float p0 = __expf(d0 + mr0[m]);
        float p1 = __expf(d1 + mr1[m]);
        sum0 += p0; sum1 += p1;
        const float4* vp = (const float4*)(Vg + m * 32);
#pragma unroll
        for (int tt = 0; tt < 8; tt++) {
            float4 vv = vp[tt];
            acc0[4 * tt] += p0 * vv.x; acc0[4 * tt + 1] += p0 * vv.y;
            acc0[4 * tt + 2] += p0 * vv.z; acc0[4 * tt + 3] += p0 * vv.w;
            acc1[4 * tt] += p1 * vv.x; acc1[4 * tt + 1] += p1 * vv.y;
            acc1[4 * tt + 2] += p1 * vv.z; acc1[4 * tt + 3] += p1 * vv.w;
        }
    }
    float i0 = 1.f / sum0, i1 = 1.f / sum1;
    float* o0 = g_xo + (long)(w * NTOK + g * 64 + r0) * C2 + h * HDIM;
    float* o1 = g_xo + (long)(w * NTOK + g * 64 + r0 + 32) * C2 + h * HDIM;
#pragma unroll
    for (int d = 0; d < HDIM; d++) { o0[d] = acc0[d] * i0; o1[d] = acc1[d] * i1; }
}

// ---------------- launcher ----------------
extern "C" void kernel_launch(void* const* d_in, const int* in_sizes, int n_in,
                              void* d_out, int out_size) {
    const float* x     = (const float*)d_in[0];
    const float* mask  = (const float*)d_in[1];
    const float* g1    = (const float*)d_in[2];
    const float* b1    = (const float*)d_in[3];
    const float* g2    = (const float*)d_in[4];
    const float* b2    = (const float*)d_in[5];
    const float* wqs   = (const float*)d_in[6];
    const float* bqs   = (const float*)d_in[7];
    const float* wqm   = (const float*)d_in[8];
    const float* bqm   = (const float*)d_in[9];
    const float* rpb   = (const float*)d_in[10];
    const float* posb  = (const float*)d_in[11];
    const float* wproj = (const float*)d_in[12];
    const float* bproj = (const float*)d_in[13];
    const float* w11   = (const float*)d_in[14];
    const float* b11   = (const float*)d_in[15];
    const float* w12   = (const float*)d_in[16];
    const float* b12   = (const float*)d_in[17];
    const float* w2    = (const float*)d_in[18];
    const float* b2f   = (const float*)d_in[19];
    const int*   rpi   = (const int*)d_in[20];
    float* out = (float*)d_out;

    const int SMEM_G192  = (128 * 200 + 64 * 200) * 2 + 16 * 68 * 4;                     // 81152
    const int SMEM_G192F = (128 * 200 + 64 * 200) * 2 + 2 * 128 * 68 * 4 + 16 * 68 * 4;  // 150784
    const int SMEM_G384  = (128 * 392 + 64 * 392) * 2 + 128 * 68 * 4;                    // 185344

    cudaFuncSetAttribute(&gemm_wmma<192, 0, 0, 0, 1, 0, 0>, cudaFuncAttributeMaxDynamicSharedMemorySize, SMEM_G192);
    cudaFuncSetAttribute(&gemm_wmma<192, 1, 0, 0, 2, 1, 0>, cudaFuncAttributeMaxDynamicSharedMemorySize, SMEM_G192);
    cudaFuncSetAttribute(&gemm_wmma<384, 0, 1, 3, 4, 2, 0>, cudaFuncAttributeMaxDynamicSharedMemorySize, SMEM_G384);
    cudaFuncSetAttribute(&gemm_wmma<192, 0, 3, 5, 6, 3, 4>, cudaFuncAttributeMaxDynamicSharedMemorySize, SMEM_G192F);
    cudaFuncSetAttribute(&gemm_wmma<384, 0, 2, 6, -1, 5, 0>, cudaFuncAttributeMaxDynamicSharedMemorySize, SMEM_G384);

    // 0-1) weight prep (two launches)
    prep_qkv_kernel<<<(2 * 576 * 192 + 255) / 256, 256>>>(wqs, wqm);
    prep_rest_kernel<<<(4 * 192 * 384 + 255) / 256, 256>>>(wproj, w11, w12, w2);
    // 2) rel-pos bias
    bias_kernel<<<(NHD * NTOK * NTOK + 255) / 256, 256>>>(rpb, rpi);
    // 3) LN1 + roll + window partition
    ln_kernel<0><<<(M_ROWS * 32) / 256, 256>>>(x, g1, b1);
    // 4-5) qkv GEMMs (direct store, padded stride 576) — launch idx 5 = ncu target
    gemm_wmma<192, 0, 0, 0, 1, 0, 0><<<768, 256, SMEM_G192>>>(bqs, nullptr, nullptr, nullptr, nullptr, CC, CC, C3, QKV_STR, 9);
    gemm_wmma<192, 1, 0, 0, 2, 1, 0><<<768, 256, SMEM_G192>>>(bqm, nullptr, nullptr, nullptr, posb, CC, CC, C3, QKV_STR, 9);
    // 6-7) attention (2 queries/thread)
    dim3 ga(NHD, NWIN);
    self_attn_kernel<<<ga, 64>>>(mask);
    mut_attn_kernel<<<ga, 64>>>(mask);
    // 8) proj + window reverse + roll + residual -> g_y
    gemm_wmma<384, 0, 1, 3, 4, 2, 0><<<768, 256, SMEM_G384>>>(bproj, nullptr, nullptr, x, nullptr, C2, C2, CC, CC, 3);
    // 9) LN2
    ln_kernel<1><<<(M_ROWS * 32) / 256, 256>>>(nullptr, g2, b2);
    // 10) fused MLP: hid1 = gelu(h2@w11+b11) * (h2@w12+b12), stride 384
    gemm_wmma<192, 0, 3, 5, 6, 3, 4><<<768, 256, SMEM_G192F>>>(b11, b12, nullptr, nullptr, nullptr, CC, CC, HID, HID_STR, 6);
    // 11) fc2 + residual -> out
    gemm_wmma<384, 0, 2, 6, -1, 5, 0><<<768, 256, SMEM_G384>>>(b2f, nullptr, out, nullptr, nullptr, HID_STR, HID_STR, CC, CC, 3);
}

// round 8
// speedup vs baseline: 1.5666x; 1.5666x over previous
#include <cuda_runtime.h>
#include <cuda_fp16.h>
#include <mma.h>
#include <cstdint>
#include <math_constants.h>
#include <math.h>

using namespace nvcuda;

// ---------------- problem constants ----------------
#define DD 6
#define HH 128
#define WW 128
#define CC 180
#define NHD 6
#define HDIM 30
#define NWIN 768
#define NTOK 128
#define M_ROWS 98304
#define C3 540
#define C2 360
#define HID 360
#define QKV_STR 576
#define HID_STR 384
#define ATT_SCALE 0.18257418583505536f

// ---------------- scratch ----------------
__device__ float g_xw[M_ROWS * CC];
__device__ float g_qkvS[M_ROWS * QKV_STR];
__device__ float g_qkvM[M_ROWS * QKV_STR];
__device__ float g_xo[M_ROWS * C2];
__device__ float g_y[M_ROWS * CC];
__device__ float g_h2[M_ROWS * CC];
__device__ float g_hid1[M_ROWS * HID_STR];
__device__ float g_bias6[NHD * NTOK * NTOK];
__device__ __half g_wT_qs[576 * 192];
__device__ __half g_wT_qm[576 * 192];
__device__ __half g_wT_pr[192 * 384];
__device__ __half g_wT_f11[384 * 192];
__device__ __half g_wT_f12[384 * 192];
__device__ __half g_wT_f2[192 * 384];

template <int ID> __device__ __forceinline__ float* fbuf() {
    if (ID == 0) return g_xw;
    if (ID == 1) return g_qkvS;
    if (ID == 2) return g_qkvM;
    if (ID == 3) return g_xo;
    if (ID == 4) return g_y;
    if (ID == 5) return g_h2;
    return g_hid1;
}
template <int ID> __device__ __forceinline__ __half* wbuf() {
    if (ID == 0) return g_wT_qs;
    if (ID == 1) return g_wT_qm;
    if (ID == 2) return g_wT_pr;
    if (ID == 3) return g_wT_f11;
    if (ID == 4) return g_wT_f12;
    return g_wT_f2;
}

__device__ __forceinline__ int row_to_img(int r) {
    int win = r >> 7, n = r & 127;
    int dwin = win >> 8, rem = win & 255;
    int hwin = rem >> 4, wwin = rem & 15;
    int nd = n >> 6, nh = (n >> 3) & 7, nw = n & 7;
    int sd = dwin * 2 + nd + 1; if (sd >= 6) sd -= 6;
    int sh = (hwin * 8 + nh + 4) & 127;
    int sw = (wwin * 8 + nw + 4) & 127;
    return (sd * 128 + sh) * 128 + sw;
}

// ---------------- weight prep ----------------
__device__ __forceinline__ void prep_one(const float* w, __half* wt, int idx,
                                         int K, int N, int Kpad, int Npad) {
    int n = idx / Kpad, k = idx % Kpad;
    wt[idx] = (n < N && k < K) ? __float2half(w[(long)k * N + n]) : __float2half(0.f);
}
__global__ void prep_qkv_kernel(const float* __restrict__ wqs, const float* __restrict__ wqm) {
    int idx = blockIdx.x * blockDim.x + threadIdx.x;
    if (idx < 576 * 192) prep_one(wqs, g_wT_qs, idx, CC, C3, 192, 576);
    else if (idx < 2 * 576 * 192) prep_one(wqm, g_wT_qm, idx - 576 * 192, CC, C3, 192, 576);
}
__global__ void prep_rest_kernel(const float* __restrict__ wproj, const float* __restrict__ w11,
                                 const float* __restrict__ w12, const float* __restrict__ w2) {
    int idx = blockIdx.x * blockDim.x + threadIdx.x;
    const int S = 192 * 384;
    if (idx < S) prep_one(wproj, g_wT_pr, idx, C2, CC, 384, 192);
    else if (idx < 2 * S) prep_one(w11, g_wT_f11, idx - S, CC, HID, 192, 384);
    else if (idx < 3 * S) prep_one(w12, g_wT_f12, idx - 2 * S, CC, HID, 192, 384);
    else if (idx < 4 * S) prep_one(w2, g_wT_f2, idx - 3 * S, HID, CC, 384, 192);
}

// ---------------- rel-pos bias gather ----------------
__global__ void bias_kernel(const float* __restrict__ rpb, const int* __restrict__ rpi) {
    int idx = blockIdx.x * blockDim.x + threadIdx.x;
    if (idx >= NHD * NTOK * NTOK) return;
    int h = idx / (NTOK * NTOK), ij = idx % (NTOK * NTOK);
    g_bias6[idx] = rpb[rpi[ij] * NHD + h];
}

// ---------------- LayerNorm ----------------
template <int MODE>
__global__ __launch_bounds__(256) void ln_kernel(const float* __restrict__ in,
                                                 const float* __restrict__ gg,
                                                 const float* __restrict__ bb) {
    const float* src_buf = (MODE == 0) ? in : fbuf<4>();
    float* dst_buf = (MODE == 0) ? fbuf<0>() : fbuf<5>();
    int gw = (blockIdx.x * blockDim.x + threadIdx.x) >> 5;
    int lane = threadIdx.x & 31;
    if (gw >= M_ROWS) return;
    int srcrow = (MODE == 0) ? row_to_img(gw) : gw;
    const float* rowp = src_buf + (long)srcrow * CC;
    float vals[6];
    float s = 0.f, ss = 0.f;
    int cnt = 0;
    for (int c = lane; c < CC; c += 32) { float v = rowp[c]; vals[cnt++] = v; s += v; ss += v * v; }
#pragma unroll
    for (int o = 16; o > 0; o >>= 1) {
        s  += __shfl_xor_sync(0xffffffffu, s, o);
        ss += __shfl_xor_sync(0xffffffffu, ss, o);
    }
    float mean = s * (1.f / CC);
    float var = ss * (1.f / CC) - mean * mean;
    float rstd = rsqrtf(var + 1e-5f);
    float* orow = dst_buf + (long)gw * CC;
    cnt = 0;
    for (int c = lane; c < CC; c += 32)
        orow[c] = (vals[cnt++] - mean) * rstd * gg[c] + bb[c];
}

// ---------------- wmma fp16 GEMM (unchanged from R7) ----------------
template <int KPAD, int ADD_PB, int MODE, int SRC, int DST, int WID, int WID2>
__global__ __launch_bounds__(256) void gemm_wmma(const float* __restrict__ bias,
                                                 const float* __restrict__ bias2,
                                                 float* __restrict__ CoutExt,
                                                 const float* __restrict__ extA,
                                                 const float* __restrict__ pb,
                                                 int Kreal, int Astride, int Nreal,
                                                 int Nstride, int Ntiles) {
    const float* A = fbuf<SRC>();
    const __half* BT1 = wbuf<WID>();
    const __half* BT2 = wbuf<WID2>();
    float* Cout = (DST >= 0) ? fbuf<(DST >= 0 ? DST : 0)>() : CoutExt;
    const float* addsrc = (MODE == 1) ? extA : fbuf<4>();
    constexpr int NPASS = (MODE == 3) ? 2 : 1;

    constexpr int LDA = KPAD + 8;
    constexpr int LDC = 68;
    extern __shared__ __align__(16) char smem[];
    __half* As = (__half*)smem;
    __half* Bs = As + 128 * LDA;
    float*  Cs = (float*)(Bs + 64 * LDA);
    float*  Cs2 = (MODE == 3) ? (Cs + 128 * LDC) : Cs;
    float*  biasS = (MODE == 3) ? (Cs2 + 128 * LDC) : Cs;

    int tid = threadIdx.x, wid = tid >> 5;
    int m0 = blockIdx.x * 128;

    constexpr int KF4 = KPAD / 4;
    int kreal4 = Kreal >> 2;
    for (int idx = tid; idx < 128 * KF4; idx += 256) {
        int row = idx / KF4, c4 = idx % KF4;
        uint2 val = make_uint2(0u, 0u);
        if (c4 < kreal4) {
            float4 a = *(const float4*)(A + (long)(m0 + row) * Astride + c4 * 4);
            if (ADD_PB) {
                float4 p = *(const float4*)(pb + ((m0 + row) & 63) * CC + c4 * 4);
                a.x += p.x; a.y += p.y; a.z += p.z; a.w += p.w;
            }
            __half2 h0 = __floats2half2_rn(a.x, a.y);
            __half2 h1 = __floats2half2_rn(a.z, a.w);
            val.x = *(uint32_t*)&h0;
            val.y = *(uint32_t*)&h1;
        }
        *(uint2*)(As + row * LDA + c4 * 4) = val;
    }

    int wm = (wid & 3) * 32;
    int wn = (wid >> 2) * 32;

    for (int t = 0; t < Ntiles; t++) {
        int n0 = t * 64;
#pragma unroll
        for (int pass = 0; pass < NPASS; pass++) {
            const __half* Bp = (pass == 0) ? BT1 : BT2;
            const float* bp = (pass == 0) ? bias : bias2;
            float* Cdst = (pass == 0) ? Cs : Cs2;

            for (int idx = tid; idx < 16 * 64; idx += 256) {
                int row = idx >> 6, c = idx & 63;
                biasS[row * LDC + c] = (n0 + c < Nreal) ? bp[n0 + c] : 0.f;
            }
            constexpr int BU4 = KPAD / 8;
            for (int idx = tid; idx < 64 * BU4; idx += 256) {
                int n = idx / BU4, c = idx % BU4;
                uint4 v = *(const uint4*)(Bp + (long)(n0 + n) * KPAD + c * 8);
                *(uint4*)(Bs + n * LDA + c * 8) = v;
            }
            __syncthreads();

            wmma::fragment<wmma::accumulator, 16, 16, 16, float> acc[2][2];
#pragma unroll
            for (int i = 0; i < 2; i++)
#pragma unroll
                for (int j = 0; j < 2; j++)
                    wmma::load_matrix_sync(acc[i][j], biasS + wn + j * 16, LDC, wmma::mem_row_major);

#pragma unroll
            for (int k = 0; k < KPAD; k += 16) {
                wmma::fragment<wmma::matrix_a, 16, 16, 16, __half, wmma::row_major> af[2];
                wmma::fragment<wmma::matrix_b, 16, 16, 16, __half, wmma::col_major> bf[2];
#pragma unroll
                for (int i = 0; i < 2; i++)
                    wmma::load_matrix_sync(af[i], As + (wm + i * 16) * LDA + k, LDA);
#pragma unroll
                for (int j = 0; j < 2; j++)
                    wmma::load_matrix_sync(bf[j], Bs + (wn + j * 16) * LDA + k, LDA);
#pragma unroll
                for (int i = 0; i < 2; i++)
#pragma unroll
                    for (int j = 0; j < 2; j++)
                        wmma::mma_sync(acc[i][j], af[i], bf[j], acc[i][j]);
            }

            if (MODE == 0) {
#pragma unroll
                for (int i = 0; i < 2; i++)
#pragma unroll
                    for (int j = 0; j < 2; j++)
                        wmma::store_matrix_sync(Cout + (long)(m0 + wm + i * 16) * Nstride + n0 + wn + j * 16,
                                                acc[i][j], Nstride, wmma::mem_row_major);
            } else {
#pragma unroll
                for (int i = 0; i < 2; i++)
#pragma unroll
                    for (int j = 0; j < 2; j++)
                        wmma::store_matrix_sync(Cdst + (wm + i * 16) * LDC + wn + j * 16,
                                                acc[i][j], LDC, wmma::mem_row_major);
            }
            __syncthreads();
        }

        if (MODE != 0) {
            int nlim = (MODE == 3) ? Nstride : Nreal;
            for (int idx = tid; idx < 128 * 16; idx += 256) {
                int row = idx >> 4, c4 = (idx & 15) * 4;
                int n = n0 + c4;
                if (n + 4 <= nlim) {
                    float4 v = *(float4*)(Cs + row * LDC + c4);
                    int r = m0 + row;
                    if (MODE == 1) {
                        int img = row_to_img(r);
                        const float4 xr = *(const float4*)(addsrc + (long)img * CC + n);
                        v.x += xr.x; v.y += xr.y; v.z += xr.z; v.w += xr.w;
                        *(float4*)(Cout + (long)img * CC + n) = v;
                    } else if (MODE == 2) {
                        const float4 yr = *(const float4*)(addsrc + (long)r * CC + n);
                        v.x += yr.x; v.y += yr.y; v.z += yr.z; v.w += yr.w;
                        *(float4*)(Cout + (long)r * CC + n) = v;
                    } else {
                        float4 v2 = *(float4*)(Cs2 + row * LDC + c4);
                        float4 o;
                        o.x = 0.5f * v.x * (1.f + erff(v.x * 0.70710678f)) * v2.x;
                        o.y = 0.5f * v.y * (1.f + erff(v.y * 0.70710678f)) * v2.y;
                        o.z = 0.5f * v.z * (1.f + erff(v.z * 0.70710678f)) * v2.z;
                        o.w = 0.5f * v.w * (1.f + erff(v.w * 0.70710678f)) * v2.w;
                        *(float4*)(Cout + (long)r * Nstride + n) = o;
                    }
                }
            }
            __syncthreads();
        }
    }
}

// ---------------- self attention via wmma ----------------
// Block (h, w), 256 threads = 8 warps. S = QK^T (HMMA) -> softmax -> P fp16 -> PV (HMMA).
#define LQ 40    // half stride of Q/K/V tiles
#define LS 132   // float stride of S
#define LP 136   // half stride of P
#define LO 36    // float stride of O (reuses Q/K region)
__global__ __launch_bounds__(256) void self_attn_kernel(const float* __restrict__ mask) {
    int h = blockIdx.x, w = blockIdx.y;
    int tid = threadIdx.x, wid = tid >> 5, lane = tid & 31;
    extern __shared__ __align__(16) char smraw[];
    __half* Qs = (__half*)smraw;                 // [128][LQ]
    __half* Ks = Qs + 128 * LQ;                  // [128][LQ]
    __half* Vs = Ks + 128 * LQ;                  // [128][LQ]
    float* S = (float*)(Vs + 128 * LQ);          // [128][LS]
    __half* P = (__half*)(S + 128 * LS);         // [128][LP]
    float* rsum = (float*)(P + 128 * LP);        // [128]
    float* Of = (float*)Qs;                      // [128][LO] reuse after S phase

    const float* base = g_qkvS + (long)w * NTOK * QKV_STR + h * HDIM;

    // stage Q (scaled), K, V as fp16
    {
        int row = tid >> 1, part = tid & 1;
        const float* src = base + (long)row * QKV_STR;
        int d0 = part * 15;
#pragma unroll
        for (int dd = 0; dd < 15; dd++) {
            int d = d0 + dd;
            Qs[row * LQ + d] = __float2half(src[d] * ATT_SCALE);
            Ks[row * LQ + d] = __float2half(src[180 + d]);
            Vs[row * LQ + d] = __float2half(src[360 + d]);
        }
        if (part) {
            Qs[row * LQ + 30] = __float2half(0.f); Qs[row * LQ + 31] = __float2half(0.f);
            Ks[row * LQ + 30] = __float2half(0.f); Ks[row * LQ + 31] = __float2half(0.f);
            Vs[row * LQ + 30] = __float2half(0.f); Vs[row * LQ + 31] = __float2half(0.f);
        }
    }
    __syncthreads();

    // S = Q @ K^T : warp wid handles rows [wid*16, wid*16+16), all 8 n-tiles
    {
        wmma::fragment<wmma::accumulator, 16, 16, 16, float> acc[8];
#pragma unroll
        for (int j = 0; j < 8; j++) wmma::fill_fragment(acc[j], 0.f);
#pragma unroll
        for (int k = 0; k < 2; k++) {
            wmma::fragment<wmma::matrix_a, 16, 16, 16, __half, wmma::row_major> af;
            wmma::load_matrix_sync(af, Qs + (wid * 16) * LQ + k * 16, LQ);
#pragma unroll
            for (int j = 0; j < 8; j++) {
                wmma::fragment<wmma::matrix_b, 16, 16, 16, __half, wmma::col_major> bf;
                wmma::load_matrix_sync(bf, Ks + (j * 16) * LQ + k * 16, LQ);
                wmma::mma_sync(acc[j], af, bf, acc[j]);
            }
        }
#pragma unroll
        for (int j = 0; j < 8; j++)
            wmma::store_matrix_sync(S + (wid * 16) * LS + j * 16, acc[j], LS, wmma::mem_row_major);
    }
    __syncthreads();

    // softmax (no max pass): warp handles 16 rows; lanes along columns (float4)
    {
        const float* bbase = g_bias6 + h * (NTOK * NTOK);
        const float* mbase = mask + (long)w * (NTOK * NTOK);
        for (int rr = 0; rr < 16; rr++) {
            int r = wid * 16 + rr;
            float4 s4 = *(float4*)(S + r * LS + lane * 4);
            float4 b4 = *(const float4*)(bbase + r * NTOK + lane * 4);
            float4 m4 = *(const float4*)(mbase + r * NTOK + lane * 4);
            float p0 = __expf(s4.x + b4.x + m4.x);
            float p1 = __expf(s4.y + b4.y + m4.y);
            float p2 = __expf(s4.z + b4.z + m4.z);
            float p3 = __expf(s4.w + b4.w + m4.w);
            __half2 h0 = __floats2half2_rn(p0, p1);
            __half2 h1 = __floats2half2_rn(p2, p3);
            uint2 pk = make_uint2(*(uint32_t*)&h0, *(uint32_t*)&h1);
            *(uint2*)(P + r * LP + lane * 4) = pk;
            float psum = p0 + p1 + p2 + p3;
#pragma unroll
            for (int o = 16; o > 0; o >>= 1) psum += __shfl_xor_sync(0xffffffffu, psum, o);
            if (lane == 0) rsum[r] = 1.f / psum;
        }
    }
    __syncthreads();

    // O = P @ V : warp wid rows [wid*16..), 2 n-tiles of 16
    {
        wmma::fragment<wmma::accumulator, 16, 16, 16, float> acc[2];
        wmma::fill_fragment(acc[0], 0.f);
        wmma::fill_fragment(acc[1], 0.f);
#pragma unroll
        for (int k = 0; k < 8; k++) {
            wmma::fragment<wmma::matrix_a, 16, 16, 16, __half, wmma::row_major> pf;
            wmma::load_matrix_sync(pf, P + (wid * 16) * LP + k * 16, LP);
#pragma unroll
            for (int j = 0; j < 2; j++) {
                wmma::fragment<wmma::matrix_b, 16, 16, 16, __half, wmma::row_major> vf;
                wmma::load_matrix_sync(vf, Vs + (k * 16) * LQ + j * 16, LQ);
                wmma::mma_sync(acc[j], pf, vf, acc[j]);
            }
        }
#pragma unroll
        for (int j = 0; j < 2; j++)
            wmma::store_matrix_sync(Of + (wid * 16) * LO + j * 16, acc[j], LO, wmma::mem_row_major);
    }
    __syncthreads();

    // scale + write out
    {
        int row = tid >> 1, part = tid & 1;
        float inv = rsum[row];
        float* orow = g_xo + (long)(w * NTOK + row) * C2 + CC + h * HDIM;
        int d0 = part * 15;
#pragma unroll
        for (int dd = 0; dd < 15; dd++)
            orow[d0 + dd] = Of[row * LO + d0 + dd] * inv;
    }
}

// ---------------- mutual attention via wmma (two 64x64 groups) ----------------
#define LSM 68
#define LPM 72
__global__ __launch_bounds__(256) void mut_attn_kernel(const float* __restrict__ mask) {
    int h = blockIdx.x, w = blockIdx.y;
    int tid = threadIdx.x, wid = tid >> 5, lane = tid & 31;
    extern __shared__ __align__(16) char smraw[];
    __half* Qs = (__half*)smraw;                 // [128][LQ] group-ordered queries
    __half* Ks = Qs + 128 * LQ;                  // [128][LQ]
    __half* Vs = Ks + 128 * LQ;                  // [128][LQ]
    float* S = (float*)(Vs + 128 * LQ);          // 2 x [64][LSM]
    __half* P = (__half*)(S + 2 * 64 * LSM);     // 2 x [64][LPM]
    float* rsum = (float*)(P + 2 * 64 * LPM);    // [128]
    float* Of = (float*)Qs;                      // [128][LO]

    const float* base = g_qkvM + (long)w * NTOK * QKV_STR + h * HDIM;

    // stage: row i queries from opposite half; K/V from token i
    {
        int row = tid >> 1, part = tid & 1;
        int qt = (row < 64) ? (64 + row) : (row - 64);
        const float* qsrc = base + (long)qt * QKV_STR;
        const float* ksrc = base + (long)row * QKV_STR;
        int d0 = part * 15;
#pragma unroll
        for (int dd = 0; dd < 15; dd++) {
            int d = d0 + dd;
            Qs[row * LQ + d] = __float2half(qsrc[d] * ATT_SCALE);
            Ks[row * LQ + d] = __float2half(ksrc[180 + d]);
            Vs[row * LQ + d] = __float2half(ksrc[360 + d]);
        }
        if (part) {
            Qs[row * LQ + 30] = __float2half(0.f); Qs[row * LQ + 31] = __float2half(0.f);
            Ks[row * LQ + 30] = __float2half(0.f); Ks[row * LQ + 31] = __float2half(0.f);
            Vs[row * LQ + 30] = __float2half(0.f); Vs[row * LQ + 31] = __float2half(0.f);
        }
    }
    __syncthreads();

    int g = wid >> 2, mt = wid & 3;

    // S_g = Q_g @ K_g^T (64x64)
    {
        wmma::fragment<wmma::accumulator, 16, 16, 16, float> acc[4];
#pragma unroll
        for (int j = 0; j < 4; j++) wmma::fill_fragment(acc[j], 0.f);
#pragma unroll
        for (int k = 0; k < 2; k++) {
            wmma::fragment<wmma::matrix_a, 16, 16, 16, __half, wmma::row_major> af;
            wmma::load_matrix_sync(af, Qs + (g * 64 + mt * 16) * LQ + k * 16, LQ);
#pragma unroll
            for (int j = 0; j < 4; j++) {
                wmma::fragment<wmma::matrix_b, 16, 16, 16, __half, wmma::col_major> bf;
                wmma::load_matrix_sync(bf, Ks + (g * 64 + j * 16) * LQ + k * 16, LQ);
                wmma::mma_sync(acc[j], af, bf, acc[j]);
            }
        }
#pragma unroll
        for (int j = 0; j < 4; j++)
            wmma::store_matrix_sync(S + g * 64 * LSM + (mt * 16) * LSM + j * 16, acc[j], LSM, wmma::mem_row_major);
    }
    __syncthreads();

    // softmax: warp handles 16 rows (global r in [wid*16, wid*16+16)); lanes = 2 cols each
    {
        const float* mbase = mask + (long)w * (NTOK * NTOK);
        for (int rr = 0; rr < 16; rr++) {
            int r = wid * 16 + rr;
            int gg = r >> 6, i = r & 63;
            float2 s2 = *(float2*)(S + gg * 64 * LSM + i * LSM + lane * 2);
            float2 m2 = *(const float2*)(mbase + i * NTOK + lane * 2);
            float p0 = __expf(s2.x + m2.x);
            float p1 = __expf(s2.y + m2.y);
            __half2 hp = __floats2half2_rn(p0, p1);
            *(uint32_t*)(P + gg * 64 * LPM + i * LPM + lane * 2) = *(uint32_t*)&hp;
            float psum = p0 + p1;
#pragma unroll
            for (int o = 16; o > 0; o >>= 1) psum += __shfl_xor_sync(0xffffffffu, psum, o);
            if (lane == 0) rsum[r] = 1.f / psum;
        }
    }
    __syncthreads();

    // O_g = P_g @ V_g
    {
        wmma::fragment<wmma::accumulator, 16, 16, 16, float> acc[2];
        wmma::fill_fragment(acc[0], 0.f);
        wmma::fill_fragment(acc[1], 0.f);
#pragma unroll
        for (int k = 0; k < 4; k++) {
            wmma::fragment<wmma::matrix_a, 16, 16, 16, __half, wmma::row_major> pf;
            wmma::load_matrix_sync(pf, P + g * 64 * LPM + (mt * 16) * LPM + k * 16, LPM);
#pragma unroll
            for (int j = 0; j < 2; j++) {
                wmma::fragment<wmma::matrix_b, 16, 16, 16, __half, wmma::row_major> vf;
                wmma::load_matrix_sync(vf, Vs + (g * 64 + k * 16) * LQ + j * 16, LQ);
                wmma::mma_sync(acc[j], pf, vf, acc[j]);
            }
        }
#pragma unroll
        for (int j = 0; j < 2; j++)
            wmma::store_matrix_sync(Of + (g * 64 + mt * 16) * LO + j * 16, acc[j], LO, wmma::mem_row_major);
    }
    __syncthreads();

    {
        int row = tid >> 1, part = tid & 1;
        float inv = rsum[row];
        float* orow = g_xo + (long)(w * NTOK + row) * C2 + h * HDIM;
        int d0 = part * 15;
#pragma unroll
        for (int dd = 0; dd < 15; dd++)
            orow[d0 + dd] = Of[row * LO + d0 + dd] * inv;
    }
}

// ---------------- launcher ----------------
extern "C" void kernel_launch(void* const* d_in, const int* in_sizes, int n_in,
                              void* d_out, int out_size) {
    const float* x     = (const float*)d_in[0];
    const float* mask  = (const float*)d_in[1];
    const float* g1    = (const float*)d_in[2];
    const float* b1    = (const float*)d_in[3];
    const float* g2    = (const float*)d_in[4];
    const float* b2    = (const float*)d_in[5];
    const float* wqs   = (const float*)d_in[6];
    const float* bqs   = (const float*)d_in[7];
    const float* wqm   = (const float*)d_in[8];
    const float* bqm   = (const float*)d_in[9];
    const float* rpb   = (const float*)d_in[10];
    const float* posb  = (const float*)d_in[11];
    const float* wproj = (const float*)d_in[12];
    const float* bproj = (const float*)d_in[13];
    const float* w11   = (const float*)d_in[14];
    const float* b11   = (const float*)d_in[15];
    const float* w12   = (const float*)d_in[16];
    const float* b12   = (const float*)d_in[17];
    const float* w2    = (const float*)d_in[18];
    const float* b2f   = (const float*)d_in[19];
    const int*   rpi   = (const int*)d_in[20];
    float* out = (float*)d_out;

    const int SMEM_G192  = (128 * 200 + 64 * 200) * 2 + 16 * 68 * 4;
    const int SMEM_G192F = (128 * 200 + 64 * 200) * 2 + 2 * 128 * 68 * 4 + 16 * 68 * 4;
    const int SMEM_G384  = (128 * 392 + 64 * 392) * 2 + 128 * 68 * 4;
    const int SMEM_SELF  = 3 * 128 * LQ * 2 + 128 * LS * 4 + 128 * LP * 2 + 128 * 4;   // 133,632
    const int SMEM_MUT   = 3 * 128 * LQ * 2 + 2 * 64 * LSM * 4 + 2 * 64 * LPM * 2 + 128 * 4; // 84,480

    cudaFuncSetAttribute(&gemm_wmma<192, 0, 0, 0, 1, 0, 0>, cudaFuncAttributeMaxDynamicSharedMemorySize, SMEM_G192);
    cudaFuncSetAttribute(&gemm_wmma<192, 1, 0, 0, 2, 1, 0>, cudaFuncAttributeMaxDynamicSharedMemorySize, SMEM_G192);
    cudaFuncSetAttribute(&gemm_wmma<384, 0, 1, 3, 4, 2, 0>, cudaFuncAttributeMaxDynamicSharedMemorySize, SMEM_G384);
    cudaFuncSetAttribute(&gemm_wmma<192, 0, 3, 5, 6, 3, 4>, cudaFuncAttributeMaxDynamicSharedMemorySize, SMEM_G192F);
    cudaFuncSetAttribute(&gemm_wmma<384, 0, 2, 6, -1, 5, 0>, cudaFuncAttributeMaxDynamicSharedMemorySize, SMEM_G384);
    cudaFuncSetAttribute(self_attn_kernel, cudaFuncAttributeMaxDynamicSharedMemorySize, SMEM_SELF);
    cudaFuncSetAttribute(mut_attn_kernel,  cudaFuncAttributeMaxDynamicSharedMemorySize, SMEM_MUT);

    // launch order chosen so ncu's fixed skip lands on gemm_wmma (qkv_self)
    prep_qkv_kernel<<<(2 * 576 * 192 + 255) / 256, 256>>>(wqs, wqm);                       // 0
    ln_kernel<0><<<(M_ROWS * 32) / 256, 256>>>(x, g1, b1);                                 // 1
    prep_rest_kernel<<<(4 * 192 * 384 + 255) / 256, 256>>>(wproj, w11, w12, w2);           // 2
    gemm_wmma<192, 0, 0, 0, 1, 0, 0><<<768, 256, SMEM_G192>>>(bqs, nullptr, nullptr, nullptr, nullptr, CC, CC, C3, QKV_STR, 9);   // 3 <- ncu target
    gemm_wmma<192, 1, 0, 0, 2, 1, 0><<<768, 256, SMEM_G192>>>(bqm, nullptr, nullptr, nullptr, posb, CC, CC, C3, QKV_STR, 9);      // 4
    bias_kernel<<<(NHD * NTOK * NTOK + 255) / 256, 256>>>(rpb, rpi);                       // 5
    dim3 ga(NHD, NWIN);
    self_attn_kernel<<<ga, 256, SMEM_SELF>>>(mask);                                        // 6
    mut_attn_kernel<<<ga, 256, SMEM_MUT>>>(mask);                                          // 7
    gemm_wmma<384, 0, 1, 3, 4, 2, 0><<<768, 256, SMEM_G384>>>(bproj, nullptr, nullptr, x, nullptr, C2, C2, CC, CC, 3);            // 8
    ln_kernel<1><<<(M_ROWS * 32) / 256, 256>>>(nullptr, g2, b2);                           // 9
    gemm_wmma<192, 0, 3, 5, 6, 3, 4><<<768, 256, SMEM_G192F>>>(b11, b12, nullptr, nullptr, nullptr, CC, CC, HID, HID_STR, 6);     // 10
    gemm_wmma<384, 0, 2, 6, -1, 5, 0><<<768, 256, SMEM_G384>>>(b2f, nullptr, out, nullptr, nullptr, HID_STR, HID_STR, CC, CC, 3); // 11
}

// round 9
// speedup vs baseline: 1.7230x; 1.0998x over previous
#include <cuda_runtime.h>
#include <cuda_fp16.h>
#include <mma.h>
#include <cstdint>
#include <math_constants.h>
#include <math.h>

using namespace nvcuda;

// ---------------- problem constants ----------------
#define DD 6
#define HH 128
#define WW 128
#define CC 180
#define NHD 6
#define HDIM 30
#define NWIN 768
#define NTOK 128
#define M_ROWS 98304
#define C3 540
#define C2 360
#define HID 360
#define QKV_STR 576
#define HID_STR 384
#define ATT_SCALE 0.18257418583505536f

// ---------------- scratch ----------------
__device__ float g_xw[M_ROWS * CC];
__device__ float g_qkvS[M_ROWS * QKV_STR];
__device__ float g_qkvM[M_ROWS * QKV_STR];
__device__ float g_xo[M_ROWS * C2];
__device__ float g_y[M_ROWS * CC];
__device__ float g_h2[M_ROWS * CC];
__device__ float g_hid1[M_ROWS * HID_STR];
__device__ float g_bias6[NHD * NTOK * NTOK];
__device__ __half g_wT_qs[576 * 192];
__device__ __half g_wT_qm[576 * 192];
__device__ __half g_wT_pr[192 * 384];
__device__ __half g_wT_f11[384 * 192];
__device__ __half g_wT_f12[384 * 192];
__device__ __half g_wT_f2[192 * 384];

template <int ID> __device__ __forceinline__ float* fbuf() {
    if (ID == 0) return g_xw;
    if (ID == 1) return g_qkvS;
    if (ID == 2) return g_qkvM;
    if (ID == 3) return g_xo;
    if (ID == 4) return g_y;
    if (ID == 5) return g_h2;
    return g_hid1;
}
template <int ID> __device__ __forceinline__ __half* wbuf() {
    if (ID == 0) return g_wT_qs;
    if (ID == 1) return g_wT_qm;
    if (ID == 2) return g_wT_pr;
    if (ID == 3) return g_wT_f11;
    if (ID == 4) return g_wT_f12;
    return g_wT_f2;
}

__device__ __forceinline__ int row_to_img(int r) {
    int win = r >> 7, n = r & 127;
    int dwin = win >> 8, rem = win & 255;
    int hwin = rem >> 4, wwin = rem & 15;
    int nd = n >> 6, nh = (n >> 3) & 7, nw = n & 7;
    int sd = dwin * 2 + nd + 1; if (sd >= 6) sd -= 6;
    int sh = (hwin * 8 + nh + 4) & 127;
    int sw = (wwin * 8 + nw + 4) & 127;
    return (sd * 128 + sh) * 128 + sw;
}

// ---------------- weight prep ----------------
__device__ __forceinline__ void prep_one(const float* w, __half* wt, int idx,
                                         int K, int N, int Kpad, int Npad) {
    int n = idx / Kpad, k = idx % Kpad;
    wt[idx] = (n < N && k < K) ? __float2half(w[(long)k * N + n]) : __float2half(0.f);
}
__global__ void prep_qkv_kernel(const float* __restrict__ wqs, const float* __restrict__ wqm) {
    int idx = blockIdx.x * blockDim.x + threadIdx.x;
    if (idx < 576 * 192) prep_one(wqs, g_wT_qs, idx, CC, C3, 192, 576);
    else if (idx < 2 * 576 * 192) prep_one(wqm, g_wT_qm, idx - 576 * 192, CC, C3, 192, 576);
}
__global__ void prep_rest_kernel(const float* __restrict__ wproj, const float* __restrict__ w11,
                                 const float* __restrict__ w12, const float* __restrict__ w2) {
    int idx = blockIdx.x * blockDim.x + threadIdx.x;
    const int S = 192 * 384;
    if (idx < S) prep_one(wproj, g_wT_pr, idx, C2, CC, 384, 192);
    else if (idx < 2 * S) prep_one(w11, g_wT_f11, idx - S, CC, HID, 192, 384);
    else if (idx < 3 * S) prep_one(w12, g_wT_f12, idx - 2 * S, CC, HID, 192, 384);
    else if (idx < 4 * S) prep_one(w2, g_wT_f2, idx - 3 * S, HID, CC, 384, 192);
}

// ---------------- rel-pos bias gather ----------------
__global__ void bias_kernel(const float* __restrict__ rpb, const int* __restrict__ rpi) {
    int idx = blockIdx.x * blockDim.x + threadIdx.x;
    if (idx >= NHD * NTOK * NTOK) return;
    int h = idx / (NTOK * NTOK), ij = idx % (NTOK * NTOK);
    g_bias6[idx] = rpb[rpi[ij] * NHD + h];
}

// ---------------- LayerNorm ----------------
template <int MODE>
__global__ __launch_bounds__(256) void ln_kernel(const float* __restrict__ in,
                                                 const float* __restrict__ gg,
                                                 const float* __restrict__ bb) {
    const float* src_buf = (MODE == 0) ? in : fbuf<4>();
    float* dst_buf = (MODE == 0) ? fbuf<0>() : fbuf<5>();
    int gw = (blockIdx.x * blockDim.x + threadIdx.x) >> 5;
    int lane = threadIdx.x & 31;
    if (gw >= M_ROWS) return;
    int srcrow = (MODE == 0) ? row_to_img(gw) : gw;
    const float* rowp = src_buf + (long)srcrow * CC;
    float vals[6];
    float s = 0.f, ss = 0.f;
    int cnt = 0;
    for (int c = lane; c < CC; c += 32) { float v = rowp[c]; vals[cnt++] = v; s += v; ss += v * v; }
#pragma unroll
    for (int o = 16; o > 0; o >>= 1) {
        s  += __shfl_xor_sync(0xffffffffu, s, o);
        ss += __shfl_xor_sync(0xffffffffu, ss, o);
    }
    float mean = s * (1.f / CC);
    float var = ss * (1.f / CC) - mean * mean;
    float rstd = rsqrtf(var + 1e-5f);
    float* orow = dst_buf + (long)gw * CC;
    cnt = 0;
    for (int c = lane; c < CC; c += 32)
        orow[c] = (vals[cnt++] - mean) * rstd * gg[c] + bb[c];
}

// ---------------- wmma fp16 GEMM ----------------
// MODE 0: C = A@W^T + bias, padded Nstride, double-buffered B, direct global store.
// MODE 1: y[img] = x[img] + (A@W^T + bias)
// MODE 2: out[r] = g_y[r] + (A@W^T + bias)
// MODE 3: hid1 = gelu(A@W1^T + b1) * (A@W2^T + b2)
template <int KPAD, int ADD_PB, int MODE, int SRC, int DST, int WID, int WID2>
__global__ __launch_bounds__(256) void gemm_wmma(const float* __restrict__ bias,
                                                 const float* __restrict__ bias2,
                                                 float* __restrict__ CoutExt,
                                                 const float* __restrict__ extA,
                                                 const float* __restrict__ pb,
                                                 int Kreal, int Astride, int Nreal,
                                                 int Nstride, int Ntiles) {
    const float* A = fbuf<SRC>();
    const __half* BT1 = wbuf<WID>();
    const __half* BT2 = wbuf<WID2>();
    float* Cout = (DST >= 0) ? fbuf<(DST >= 0 ? DST : 0)>() : CoutExt;
    const float* addsrc = (MODE == 1) ? extA : fbuf<4>();
    constexpr int NPASS = (MODE == 3) ? 2 : 1;

    constexpr int LDA = KPAD + 8;
    constexpr int LDC = 68;
    extern __shared__ __align__(16) char smem[];
    __half* As = (__half*)smem;

    int tid = threadIdx.x, wid = tid >> 5;
    int m0 = blockIdx.x * 128;
    int wm = (wid & 3) * 32;
    int wn = (wid >> 2) * 32;

    // ---- stage A tile [128][KPAD] fp16 ----
    constexpr int KF4 = KPAD / 4;
    int kreal4 = Kreal >> 2;
    for (int idx = tid; idx < 128 * KF4; idx += 256) {
        int row = idx / KF4, c4 = idx % KF4;
        uint2 val = make_uint2(0u, 0u);
        if (c4 < kreal4) {
            float4 a = *(const float4*)(A + (long)(m0 + row) * Astride + c4 * 4);
            if (ADD_PB) {
                float4 p = *(const float4*)(pb + ((m0 + row) & 63) * CC + c4 * 4);
                a.x += p.x; a.y += p.y; a.z += p.z; a.w += p.w;
            }
            __half2 h0 = __floats2half2_rn(a.x, a.y);
            __half2 h1 = __floats2half2_rn(a.z, a.w);
            val.x = *(uint32_t*)&h0;
            val.y = *(uint32_t*)&h1;
        }
        *(uint2*)(As + row * LDA + c4 * 4) = val;
    }

    if (MODE == 0) {
        // ---- double-buffered pipeline ----
        constexpr int BU4 = KPAD / 8;            // 16B chunks per B row
        constexpr int NB = (64 * BU4) / 256;     // per-thread B chunks (6 for KPAD=192)
        __half* Bs0 = As + 128 * LDA;
        __half* Bs1 = Bs0 + 64 * LDA;
        float* bias0 = (float*)(Bs1 + 64 * LDA);
        float* bias1 = bias0 + 16 * LDC;

        // preload tile 0
        {
            for (int i = 0; i < NB; i++) {
                int idx = tid + i * 256;
                int n = idx / BU4, c = idx % BU4;
                *(uint4*)(Bs0 + n * LDA + c * 8) = *(const uint4*)(BT1 + (long)n * KPAD + c * 8);
            }
            for (int i = 0; i < 4; i++) {
                int idx = tid + i * 256;
                int row = idx >> 6, c = idx & 63;
                bias0[row * LDC + c] = (c < Nreal) ? bias[c] : 0.f;
            }
        }
        __syncthreads();

        for (int t = 0; t < Ntiles; t++) {
            __half* Bcur = (t & 1) ? Bs1 : Bs0;
            __half* Bnxt = (t & 1) ? Bs0 : Bs1;
            float* bcur = (t & 1) ? bias1 : bias0;
            float* bnxt = (t & 1) ? bias0 : bias1;
            int n0 = t * 64;
            bool has_next = (t + 1 < Ntiles);

            // issue next-tile loads into registers
            uint4 breg[NB];
            float creg[4];
            if (has_next) {
                int n0n = n0 + 64;
#pragma unroll
                for (int i = 0; i < NB; i++) {
                    int idx = tid + i * 256;
                    int n = idx / BU4, c = idx % BU4;
                    breg[i] = *(const uint4*)(BT1 + (long)(n0n + n) * KPAD + c * 8);
                }
#pragma unroll
                for (int i = 0; i < 4; i++) {
                    int idx = tid + i * 256;
                    int c = idx & 63;
                    creg[i] = (n0n + c < Nreal) ? bias[n0n + c] : 0.f;
                }
            }

            wmma::fragment<wmma::accumulator, 16, 16, 16, float> acc[2][2];
#pragma unroll
            for (int i = 0; i < 2; i++)
#pragma unroll
                for (int j = 0; j < 2; j++)
                    wmma::load_matrix_sync(acc[i][j], bcur + wn + j * 16, LDC, wmma::mem_row_major);

#pragma unroll
            for (int k = 0; k < KPAD; k += 16) {
                wmma::fragment<wmma::matrix_a, 16, 16, 16, __half, wmma::row_major> af[2];
                wmma::fragment<wmma::matrix_b, 16, 16, 16, __half, wmma::col_major> bf[2];
#pragma unroll
                for (int i = 0; i < 2; i++)
                    wmma::load_matrix_sync(af[i], As + (wm + i * 16) * LDA + k, LDA);
#pragma unroll
                for (int j = 0; j < 2; j++)
                    wmma::load_matrix_sync(bf[j], Bcur + (wn + j * 16) * LDA + k, LDA);
#pragma unroll
                for (int i = 0; i < 2; i++)
#pragma unroll
                    for (int j = 0; j < 2; j++)
                        wmma::mma_sync(acc[i][j], af[i], bf[j], acc[i][j]);
            }

#pragma unroll
            for (int i = 0; i < 2; i++)
#pragma unroll
                for (int j = 0; j < 2; j++)
                    wmma::store_matrix_sync(Cout + (long)(m0 + wm + i * 16) * Nstride + n0 + wn + j * 16,
                                            acc[i][j], Nstride, wmma::mem_row_major);

            if (has_next) {
#pragma unroll
                for (int i = 0; i < NB; i++) {
                    int idx = tid + i * 256;
                    int n = idx / BU4, c = idx % BU4;
                    *(uint4*)(Bnxt + n * LDA + c * 8) = breg[i];
                }
#pragma unroll
                for (int i = 0; i < 4; i++) {
                    int idx = tid + i * 256;
                    int row = idx >> 6, c = idx & 63;
                    bnxt[row * LDC + c] = creg[i];
                }
            }
            __syncthreads();
        }
        return;
    }

    // ---- non-MODE-0 path (staged epilogues) ----
    __half* Bs = As + 128 * LDA;
    float*  Cs = (float*)(Bs + 64 * LDA);
    float*  Cs2 = (MODE == 3) ? (Cs + 128 * LDC) : Cs;
    float*  biasS = (MODE == 3) ? (Cs2 + 128 * LDC) : Cs;

    for (int t = 0; t < Ntiles; t++) {
        int n0 = t * 64;
#pragma unroll
        for (int pass = 0; pass < NPASS; pass++) {
            const __half* Bp = (pass == 0) ? BT1 : BT2;
            const float* bp = (pass == 0) ? bias : bias2;
            float* Cdst = (pass == 0) ? Cs : Cs2;

            for (int idx = tid; idx < 16 * 64; idx += 256) {
                int row = idx >> 6, c = idx & 63;
                biasS[row * LDC + c] = (n0 + c < Nreal) ? bp[n0 + c] : 0.f;
            }
            constexpr int BU4 = KPAD / 8;
            for (int idx = tid; idx < 64 * BU4; idx += 256) {
                int n = idx / BU4, c = idx % BU4;
                uint4 v = *(const uint4*)(Bp + (long)(n0 + n) * KPAD + c * 8);
                *(uint4*)(Bs + n * LDA + c * 8) = v;
            }
            __syncthreads();

            wmma::fragment<wmma::accumulator, 16, 16, 16, float> acc[2][2];
#pragma unroll
            for (int i = 0; i < 2; i++)
#pragma unroll
                for (int j = 0; j < 2; j++)
                    wmma::load_matrix_sync(acc[i][j], biasS + wn + j * 16, LDC, wmma::mem_row_major);

#pragma unroll
            for (int k = 0; k < KPAD; k += 16) {
                wmma::fragment<wmma::matrix_a, 16, 16, 16, __half, wmma::row_major> af[2];
                wmma::fragment<wmma::matrix_b, 16, 16, 16, __half, wmma::col_major> bf[2];
#pragma unroll
                for (int i = 0; i < 2; i++)
                    wmma::load_matrix_sync(af[i], As + (wm + i * 16) * LDA + k, LDA);
#pragma unroll
                for (int j = 0; j < 2; j++)
                    wmma::load_matrix_sync(bf[j], Bs + (wn + j * 16) * LDA + k, LDA);
#pragma unroll
                for (int i = 0; i < 2; i++)
#pragma unroll
                    for (int j = 0; j < 2; j++)
                        wmma::mma_sync(acc[i][j], af[i], bf[j], acc[i][j]);
            }

#pragma unroll
            for (int i = 0; i < 2; i++)
#pragma unroll
                for (int j = 0; j < 2; j++)
                    wmma::store_matrix_sync(Cdst + (wm + i * 16) * LDC + wn + j * 16,
                                            acc[i][j], LDC, wmma::mem_row_major);
            __syncthreads();
        }

        int nlim = (MODE == 3) ? Nstride : Nreal;
        for (int idx = tid; idx < 128 * 16; idx += 256) {
            int row = idx >> 4, c4 = (idx & 15) * 4;
            int n = n0 + c4;
            if (n + 4 <= nlim) {
                float4 v = *(float4*)(Cs + row * LDC + c4);
                int r = m0 + row;
                if (MODE == 1) {
                    int img = row_to_img(r);
                    const float4 xr = *(const float4*)(addsrc + (long)img * CC + n);
                    v.x += xr.x; v.y += xr.y; v.z += xr.z; v.w += xr.w;
                    *(float4*)(Cout + (long)img * CC + n) = v;
                } else if (MODE == 2) {
                    const float4 yr = *(const float4*)(addsrc + (long)r * CC + n);
                    v.x += yr.x; v.y += yr.y; v.z += yr.z; v.w += yr.w;
                    *(float4*)(Cout + (long)r * CC + n) = v;
                } else {
                    float4 v2 = *(float4*)(Cs2 + row * LDC + c4);
                    float4 o;
                    o.x = 0.5f * v.x * (1.f + erff(v.x * 0.70710678f)) * v2.x;
                    o.y = 0.5f * v.y * (1.f + erff(v.y * 0.70710678f)) * v2.y;
                    o.z = 0.5f * v.z * (1.f + erff(v.z * 0.70710678f)) * v2.z;
                    o.w = 0.5f * v.w * (1.f + erff(v.w * 0.70710678f)) * v2.w;
                    *(float4*)(Cout + (long)r * Nstride + n) = o;
                }
            }
        }
        __syncthreads();
    }
}

// ---------------- self attention via wmma; P aliases S ----------------
#define LQ 40    // half stride of Q/K/V tiles
#define LS 132   // float stride of S (P fp16 aliases: half stride 2*LS)
#define LO 36
__global__ __launch_bounds__(256) void self_attn_kernel(const float* __restrict__ mask) {
    int h = blockIdx.x, w = blockIdx.y;
    int tid = threadIdx.x, wid = tid >> 5, lane = tid & 31;
    extern __shared__ __align__(16) char smraw[];
    __half* Qs = (__half*)smraw;                 // [128][LQ]
    __half* Ks = Qs + 128 * LQ;
    __half* Vs = Ks + 128 * LQ;
    float* S = (float*)(Vs + 128 * LQ);          // [128][LS]
    __half* P = (__half*)S;                      // aliased, half stride 2*LS
    float* rsum = (float*)(S + 128 * LS);        // [128]
    float* Of = (float*)Qs;                      // reuse after S phase

    const float* base = g_qkvS + (long)w * NTOK * QKV_STR + h * HDIM;

    {
        int row = tid >> 1, part = tid & 1;
        const float* src = base + (long)row * QKV_STR;
        int d0 = part * 15;
#pragma unroll
        for (int dd = 0; dd < 15; dd++) {
            int d = d0 + dd;
            Qs[row * LQ + d] = __float2half(src[d] * ATT_SCALE);
            Ks[row * LQ + d] = __float2half(src[180 + d]);
            Vs[row * LQ + d] = __float2half(src[360 + d]);
        }
        if (part) {
            Qs[row * LQ + 30] = __float2half(0.f); Qs[row * LQ + 31] = __float2half(0.f);
            Ks[row * LQ + 30] = __float2half(0.f); Ks[row * LQ + 31] = __float2half(0.f);
            Vs[row * LQ + 30] = __float2half(0.f); Vs[row * LQ + 31] = __float2half(0.f);
        }
    }
    __syncthreads();

    // S = Q @ K^T
    {
        wmma::fragment<wmma::accumulator, 16, 16, 16, float> acc[8];
#pragma unroll
        for (int j = 0; j < 8; j++) wmma::fill_fragment(acc[j], 0.f);
#pragma unroll
        for (int k = 0; k < 2; k++) {
            wmma::fragment<wmma::matrix_a, 16, 16, 16, __half, wmma::row_major> af;
            wmma::load_matrix_sync(af, Qs + (wid * 16) * LQ + k * 16, LQ);
#pragma unroll
            for (int j = 0; j < 8; j++) {
                wmma::fragment<wmma::matrix_b, 16, 16, 16, __half, wmma::col_major> bf;
                wmma::load_matrix_sync(bf, Ks + (j * 16) * LQ + k * 16, LQ);
                wmma::mma_sync(acc[j], af, bf, acc[j]);
            }
        }
#pragma unroll
        for (int j = 0; j < 8; j++)
            wmma::store_matrix_sync(S + (wid * 16) * LS + j * 16, acc[j], LS, wmma::mem_row_major);
    }
    __syncthreads();

    // softmax (no max pass); write P fp16 over S in-place
    {
        const float* bbase = g_bias6 + h * (NTOK * NTOK);
        const float* mbase = mask + (long)w * (NTOK * NTOK);
        for (int rr = 0; rr < 16; rr++) {
            int r = wid * 16 + rr;
            float4 s4 = *(float4*)(S + r * LS + lane * 4);
            float4 b4 = *(const float4*)(bbase + r * NTOK + lane * 4);
            float4 m4 = *(const float4*)(mbase + r * NTOK + lane * 4);
            float p0 = __expf(s4.x + b4.x + m4.x);
            float p1 = __expf(s4.y + b4.y + m4.y);
            float p2 = __expf(s4.z + b4.z + m4.z);
            float p3 = __expf(s4.w + b4.w + m4.w);
            __half2 h0 = __floats2half2_rn(p0, p1);
            __half2 h1 = __floats2half2_rn(p2, p3);
            uint2 pk = make_uint2(*(uint32_t*)&h0, *(uint32_t*)&h1);
            *(uint2*)(P + r * (2 * LS) + lane * 4) = pk;
            float psum = p0 + p1 + p2 + p3;
#pragma unroll
            for (int o = 16; o > 0; o >>= 1) psum += __shfl_xor_sync(0xffffffffu, psum, o);
            if (lane == 0) rsum[r] = 1.f / psum;
        }
    }
    __syncthreads();

    // O = P @ V
    {
        wmma::fragment<wmma::accumulator, 16, 16, 16, float> acc[2];
        wmma::fill_fragment(acc[0], 0.f);
        wmma::fill_fragment(acc[1], 0.f);
#pragma unroll
        for (int k = 0; k < 8; k++) {
            wmma::fragment<wmma::matrix_a, 16, 16, 16, __half, wmma::row_major> pf;
            wmma::load_matrix_sync(pf, P + (wid * 16) * (2 * LS) + k * 16, 2 * LS);
#pragma unroll
            for (int j = 0; j < 2; j++) {
                wmma::fragment<wmma::matrix_b, 16, 16, 16, __half, wmma::row_major> vf;
                wmma::load_matrix_sync(vf, Vs + (k * 16) * LQ + j * 16, LQ);
                wmma::mma_sync(acc[j], pf, vf, acc[j]);
            }
        }
#pragma unroll
        for (int j = 0; j < 2; j++)
            wmma::store_matrix_sync(Of + (wid * 16) * LO + j * 16, acc[j], LO, wmma::mem_row_major);
    }
    __syncthreads();

    {
        int row = tid >> 1, part = tid & 1;
        float inv = rsum[row];
        float* orow = g_xo + (long)(w * NTOK + row) * C2 + CC + h * HDIM;
        int d0 = part * 15;
#pragma unroll
        for (int dd = 0; dd < 15; dd++)
            orow[d0 + dd] = Of[row * LO + d0 + dd] * inv;
    }
}

// ---------------- mutual attention via wmma; P aliases S ----------------
#define LSM 68
__global__ __launch_bounds__(256) void mut_attn_kernel(const float* __restrict__ mask) {
    int h = blockIdx.x, w = blockIdx.y;
    int tid = threadIdx.x, wid = tid >> 5, lane = tid & 31;
    extern __shared__ __align__(16) char smraw[];
    __half* Qs = (__half*)smraw;
    __half* Ks = Qs + 128 * LQ;
    __half* Vs = Ks + 128 * LQ;
    float* S = (float*)(Vs + 128 * LQ);          // 2 x [64][LSM]
    __half* P = (__half*)S;                      // aliased, half stride 2*LSM
    float* rsum = (float*)(S + 2 * 64 * LSM);    // [128]
    float* Of = (float*)Qs;

    const float* base = g_qkvM + (long)w * NTOK * QKV_STR + h * HDIM;

    {
        int row = tid >> 1, part = tid & 1;
        int qt = (row < 64) ? (64 + row) : (row - 64);
        const float* qsrc = base + (long)qt * QKV_STR;
        const float* ksrc = base + (long)row * QKV_STR;
        int d0 = part * 15;
#pragma unroll
        for (int dd = 0; dd < 15; dd++) {
            int d = d0 + dd;
            Qs[row * LQ + d] = __float2half(qsrc[d] * ATT_SCALE);
            Ks[row * LQ + d] = __float2half(ksrc[180 + d]);
            Vs[row * LQ + d] = __float2half(ksrc[360 + d]);
        }
        if (part) {
            Qs[row * LQ + 30] = __float2half(0.f); Qs[row * LQ + 31] = __float2half(0.f);
            Ks[row * LQ + 30] = __float2half(0.f); Ks[row * LQ + 31] = __float2half(0.f);
            Vs[row * LQ + 30] = __float2half(0.f); Vs[row * LQ + 31] = __float2half(0.f);
        }
    }
    __syncthreads();

    int g = wid >> 2, mt = wid & 3;

    {
        wmma::fragment<wmma::accumulator, 16, 16, 16, float> acc[4];
#pragma unroll
        for (int j = 0; j < 4; j++) wmma::fill_fragment(acc[j], 0.f);
#pragma unroll
        for (int k = 0; k < 2; k++) {
            wmma::fragment<wmma::matrix_a, 16, 16, 16, __half, wmma::row_major> af;
            wmma::load_matrix_sync(af, Qs + (g * 64 + mt * 16) * LQ + k * 16, LQ);
#pragma unroll
            for (int j = 0; j < 4; j++) {
                wmma::fragment<wmma::matrix_b, 16, 16, 16, __half, wmma::col_major> bf;
                wmma::load_matrix_sync(bf, Ks + (g * 64 + j * 16) * LQ + k * 16, LQ);
                wmma::mma_sync(acc[j], af, bf, acc[j]);
            }
        }
#pragma unroll
        for (int j = 0; j < 4; j++)
            wmma::store_matrix_sync(S + g * 64 * LSM + (mt * 16) * LSM + j * 16, acc[j], LSM, wmma::mem_row_major);
    }
    __syncthreads();

    {
        const float* mbase = mask + (long)w * (NTOK * NTOK);
        for (int rr = 0; rr < 16; rr++) {
            int r = wid * 16 + rr;
            int gg = r >> 6, i = r & 63;
            float2 s2 = *(float2*)(S + gg * 64 * LSM + i * LSM + lane * 2);
            float2 m2 = *(const float2*)(mbase + i * NTOK + lane * 2);
            float p0 = __expf(s2.x + m2.x);
            float p1 = __expf(s2.y + m2.y);
            __half2 hp = __floats2half2_rn(p0, p1);
            *(uint32_t*)(P + gg * 64 * (2 * LSM) + i * (2 * LSM) + lane * 2) = *(uint32_t*)&hp;
            float psum = p0 + p1;
#pragma unroll
            for (int o = 16; o > 0; o >>= 1) psum += __shfl_xor_sync(0xffffffffu, psum, o);
            if (lane == 0) rsum[r] = 1.f / psum;
        }
    }
    __syncthreads();

    {
        wmma::fragment<wmma::accumulator, 16, 16, 16, float> acc[2];
        wmma::fill_fragment(acc[0], 0.f);
        wmma::fill_fragment(acc[1], 0.f);
#pragma unroll
        for (int k = 0; k < 4; k++) {
            wmma::fragment<wmma::matrix_a, 16, 16, 16, __half, wmma::row_major> pf;
            wmma::load_matrix_sync(pf, P + g * 64 * (2 * LSM) + (mt * 16) * (2 * LSM) + k * 16, 2 * LSM);
#pragma unroll
            for (int j = 0; j < 2; j++) {
                wmma::fragment<wmma::matrix_b, 16, 16, 16, __half, wmma::row_major> vf;
                wmma::load_matrix_sync(vf, Vs + (g * 64 + k * 16) * LQ + j * 16, LQ);
                wmma::mma_sync(acc[j], pf, vf, acc[j]);
            }
        }
#pragma unroll
        for (int j = 0; j < 2; j++)
            wmma::store_matrix_sync(Of + (g * 64 + mt * 16) * LO + j * 16, acc[j], LO, wmma::mem_row_major);
    }
    __syncthreads();

    {
        int row = tid >> 1, part = tid & 1;
        float inv = rsum[row];
        float* orow = g_xo + (long)(w * NTOK + row) * C2 + h * HDIM;
        int d0 = part * 15;
#pragma unroll
        for (int dd = 0; dd < 15; dd++)
            orow[d0 + dd] = Of[row * LO + d0 + dd] * inv;
    }
}

// ---------------- launcher ----------------
extern "C" void kernel_launch(void* const* d_in, const int* in_sizes, int n_in,
                              void* d_out, int out_size) {
    const float* x     = (const float*)d_in[0];
    const float* mask  = (const float*)d_in[1];
    const float* g1    = (const float*)d_in[2];
    const float* b1    = (const float*)d_in[3];
    const float* g2    = (const float*)d_in[4];
    const float* b2    = (const float*)d_in[5];
    const float* wqs   = (const float*)d_in[6];
    const float* bqs   = (const float*)d_in[7];
    const float* wqm   = (const float*)d_in[8];
    const float* bqm   = (const float*)d_in[9];
    const float* rpb   = (const float*)d_in[10];
    const float* posb  = (const float*)d_in[11];
    const float* wproj = (const float*)d_in[12];
    const float* bproj = (const float*)d_in[13];
    const float* w11   = (const float*)d_in[14];
    const float* b11   = (const float*)d_in[15];
    const float* w12   = (const float*)d_in[16];
    const float* b12   = (const float*)d_in[17];
    const float* w2    = (const float*)d_in[18];
    const float* b2f   = (const float*)d_in[19];
    const int*   rpi   = (const int*)d_in[20];
    float* out = (float*)d_out;

    const int SMEM_G192D = 128 * 200 * 2 + 2 * 64 * 200 * 2 + 2 * 16 * 68 * 4;          // 111104
    const int SMEM_G192F = (128 * 200 + 64 * 200) * 2 + 2 * 128 * 68 * 4 + 16 * 68 * 4; // 150784
    const int SMEM_G384  = (128 * 392 + 64 * 392) * 2 + 128 * 68 * 4;                   // 185344
    const int SMEM_SELF  = 3 * 128 * LQ * 2 + 128 * LS * 4 + 128 * 4;                   // 98816
    const int SMEM_MUT   = 3 * 128 * LQ * 2 + 2 * 64 * LSM * 4 + 128 * 4;               // 66048

    cudaFuncSetAttribute(&gemm_wmma<192, 0, 0, 0, 1, 0, 0>, cudaFuncAttributeMaxDynamicSharedMemorySize, SMEM_G192D);
    cudaFuncSetAttribute(&gemm_wmma<192, 1, 0, 0, 2, 1, 0>, cudaFuncAttributeMaxDynamicSharedMemorySize, SMEM_G192D);
    cudaFuncSetAttribute(&gemm_wmma<384, 0, 1, 3, 4, 2, 0>, cudaFuncAttributeMaxDynamicSharedMemorySize, SMEM_G384);
    cudaFuncSetAttribute(&gemm_wmma<192, 0, 3, 5, 6, 3, 4>, cudaFuncAttributeMaxDynamicSharedMemorySize, SMEM_G192F);
    cudaFuncSetAttribute(&gemm_wmma<384, 0, 2, 6, -1, 5, 0>, cudaFuncAttributeMaxDynamicSharedMemorySize, SMEM_G384);
    cudaFuncSetAttribute(self_attn_kernel, cudaFuncAttributeMaxDynamicSharedMemorySize, SMEM_SELF);
    cudaFuncSetAttribute(mut_attn_kernel,  cudaFuncAttributeMaxDynamicSharedMemorySize, SMEM_MUT);

    prep_qkv_kernel<<<(2 * 576 * 192 + 255) / 256, 256>>>(wqs, wqm);                       // 0
    ln_kernel<0><<<(M_ROWS * 32) / 256, 256>>>(x, g1, b1);                                 // 1
    prep_rest_kernel<<<(4 * 192 * 384 + 255) / 256, 256>>>(wproj, w11, w12, w2);           // 2
    gemm_wmma<192, 0, 0, 0, 1, 0, 0><<<768, 256, SMEM_G192D>>>(bqs, nullptr, nullptr, nullptr, nullptr, CC, CC, C3, QKV_STR, 9);  // 3 <- ncu target
    gemm_wmma<192, 1, 0, 0, 2, 1, 0><<<768, 256, SMEM_G192D>>>(bqm, nullptr, nullptr, nullptr, posb, CC, CC, C3, QKV_STR, 9);     // 4
    bias_kernel<<<(NHD * NTOK * NTOK + 255) / 256, 256>>>(rpb, rpi);                       // 5
    dim3 ga(NHD, NWIN);
    self_attn_kernel<<<ga, 256, SMEM_SELF>>>(mask);                                        // 6
    mut_attn_kernel<<<ga, 256, SMEM_MUT>>>(mask);                                          // 7
    gemm_wmma<384, 0, 1, 3, 4, 2, 0><<<768, 256, SMEM_G384>>>(bproj, nullptr, nullptr, x, nullptr, C2, C2, CC, CC, 3);            // 8
    ln_kernel<1><<<(M_ROWS * 32) / 256, 256>>>(nullptr, g2, b2);                           // 9
    gemm_wmma<192, 0, 3, 5, 6, 3, 4><<<768, 256, SMEM_G192F>>>(b11, b12, nullptr, nullptr, nullptr, CC, CC, HID, HID_STR, 6);     // 10
    gemm_wmma<384, 0, 2, 6, -1, 5, 0><<<768, 256, SMEM_G384>>>(b2f, nullptr, out, nullptr, nullptr, HID_STR, HID_STR, CC, CC, 3); // 11
}

// round 10
// speedup vs baseline: 1.7274x; 1.0025x over previous
#include <cuda_runtime.h>
#include <cuda_fp16.h>
#include <mma.h>
#include <cstdint>
#include <math_constants.h>
#include <math.h>

using namespace nvcuda;

// ---------------- problem constants ----------------
#define CC 180
#define NHD 6
#define HDIM 30
#define NWIN 768
#define NTOK 128
#define M_ROWS 98304
#define C3 540
#define C2 360
#define HID 360
#define QKV_STR 576
#define HID_STR 384
#define Y_STR 192
#define ATT_SCALE 0.18257418583505536f

// ---------------- scratch ----------------
__device__ __half g_xw_h[M_ROWS * CC];
__device__ float  g_qkvS[M_ROWS * QKV_STR];
__device__ float  g_qkvM[M_ROWS * QKV_STR];
__device__ __half g_xo_h[M_ROWS * C2];
__device__ float  g_y[M_ROWS * Y_STR];        // WINDOW order, padded stride
__device__ __half g_h2_h[M_ROWS * CC];
__device__ __half g_hid1_h[M_ROWS * HID_STR];
__device__ float  g_bias6[NHD * NTOK * NTOK];
__device__ __half g_wT_qs[576 * 192];
__device__ __half g_wT_qm[576 * 192];
__device__ __half g_wT_pr[192 * 384];
__device__ __half g_wT_f11[384 * 192];
__device__ __half g_wT_f12[384 * 192];
__device__ __half g_wT_f2[192 * 384];

__device__ __forceinline__ int row_to_img(int r) {
    int win = r >> 7, n = r & 127;
    int dwin = win >> 8, rem = win & 255;
    int hwin = rem >> 4, wwin = rem & 15;
    int nd = n >> 6, nh = (n >> 3) & 7, nw = n & 7;
    int sd = dwin * 2 + nd + 1; if (sd >= 6) sd -= 6;
    int sh = (hwin * 8 + nh + 4) & 127;
    int sw = (wwin * 8 + nw + 4) & 127;
    return (sd * 128 + sh) * 128 + sw;
}

// ---------------- weight prep ----------------
__device__ __forceinline__ void prep_one(const float* w, __half* wt, int idx,
                                         int K, int N, int Kpad, int Npad) {
    int n = idx / Kpad, k = idx % Kpad;
    wt[idx] = (n < N && k < K) ? __float2half(w[(long)k * N + n]) : __float2half(0.f);
}
__global__ void prep_qkv_kernel(const float* __restrict__ wqs, const float* __restrict__ wqm) {
    int idx = blockIdx.x * blockDim.x + threadIdx.x;
    if (idx < 576 * 192) prep_one(wqs, g_wT_qs, idx, CC, C3, 192, 576);
    else if (idx < 2 * 576 * 192) prep_one(wqm, g_wT_qm, idx - 576 * 192, CC, C3, 192, 576);
}
__global__ void prep_rest_kernel(const float* __restrict__ wproj, const float* __restrict__ w11,
                                 const float* __restrict__ w12, const float* __restrict__ w2) {
    int idx = blockIdx.x * blockDim.x + threadIdx.x;
    const int S = 192 * 384;
    if (idx < S) prep_one(wproj, g_wT_pr, idx, C2, CC, 384, 192);
    else if (idx < 2 * S) prep_one(w11, g_wT_f11, idx - S, CC, HID, 192, 384);
    else if (idx < 3 * S) prep_one(w12, g_wT_f12, idx - 2 * S, CC, HID, 192, 384);
    else if (idx < 4 * S) prep_one(w2, g_wT_f2, idx - 3 * S, HID, CC, 384, 192);
}

// ---------------- rel-pos bias gather ----------------
__global__ void bias_kernel(const float* __restrict__ rpb, const int* __restrict__ rpi) {
    int idx = blockIdx.x * blockDim.x + threadIdx.x;
    if (idx >= NHD * NTOK * NTOK) return;
    int h = idx / (NTOK * NTOK), ij = idx % (NTOK * NTOK);
    g_bias6[idx] = rpb[rpi[ij] * NHD + h];
}

// ---------------- LayerNorm: fp32 in -> fp16 out ----------------
// MODE 0: x (image, gather via row_to_img) -> g_xw_h
// MODE 1: g_y (window order, stride 192) -> g_h2_h
template <int MODE>
__global__ __launch_bounds__(256) void ln_kernel(const float* __restrict__ in,
                                                 const float* __restrict__ gg,
                                                 const float* __restrict__ bb) {
    int gw = (blockIdx.x * blockDim.x + threadIdx.x) >> 5;
    int lane = threadIdx.x & 31;
    if (gw >= M_ROWS) return;
    const float* rowp;
    __half* orow;
    if (MODE == 0) {
        rowp = in + (long)row_to_img(gw) * CC;
        orow = g_xw_h + (long)gw * CC;
    } else {
        rowp = g_y + (long)gw * Y_STR;
        orow = g_h2_h + (long)gw * CC;
    }
    float vals[6];
    float s = 0.f, ss = 0.f;
    int cnt = 0;
    for (int c = lane; c < CC; c += 32) { float v = rowp[c]; vals[cnt++] = v; s += v; ss += v * v; }
#pragma unroll
    for (int o = 16; o > 0; o >>= 1) {
        s  += __shfl_xor_sync(0xffffffffu, s, o);
        ss += __shfl_xor_sync(0xffffffffu, ss, o);
    }
    float mean = s * (1.f / CC);
    float var = ss * (1.f / CC) - mean * mean;
    float rstd = rsqrtf(var + 1e-5f);
    cnt = 0;
    for (int c = lane; c < CC; c += 32)
        orow[c] = __float2half((vals[cnt++] - mean) * rstd * gg[c] + bb[c]);
}

// ---------------- qkv GEMM: half A, double-buffered B, direct store ----------------
// C[M_ROWS,576] = xw_h[M_ROWS,180] @ W^T + bias (+pb on A for mutual)
template <int WID, int ADD_PB, int DSTID>
__global__ __launch_bounds__(256) void gemm_qkv(const float* __restrict__ bias,
                                                const float* __restrict__ pb) {
    constexpr int KPAD = 192, LDA = 200, LDC = 68, NTILES = 9;
    const __half* A = g_xw_h;
    const __half* BT = (WID == 0) ? g_wT_qs : g_wT_qm;
    float* Cout = (DSTID == 0) ? g_qkvS : g_qkvM;
    extern __shared__ __align__(16) char smem[];
    __half* As = (__half*)smem;
    __half* Bs0 = As + 128 * LDA;
    __half* Bs1 = Bs0 + 64 * LDA;
    float* bias0 = (float*)(Bs1 + 64 * LDA);
    float* bias1 = bias0 + 16 * LDC;

    int tid = threadIdx.x, wid = tid >> 5;
    int m0 = blockIdx.x * 128;
    int wm = (wid & 3) * 32, wn = (wid >> 2) * 32;

    // stage A [128][192] from half source (stride 180)
    constexpr int KF4 = KPAD / 4;   // 48
    constexpr int KR4 = CC / 4;     // 45
    for (int idx = tid; idx < 128 * KF4; idx += 256) {
        int row = idx / KF4, c4 = idx % KF4;
        uint2 val = make_uint2(0u, 0u);
        if (c4 < KR4) {
            val = *(const uint2*)(A + (long)(m0 + row) * CC + c4 * 4);
            if (ADD_PB) {
                __half2 h0 = *(__half2*)&val.x, h1 = *(__half2*)&val.y;
                float4 p = *(const float4*)(pb + ((m0 + row) & 63) * CC + c4 * 4);
                float2 f0 = __half22float2(h0), f1 = __half22float2(h1);
                __half2 r0 = __floats2half2_rn(f0.x + p.x, f0.y + p.y);
                __half2 r1 = __floats2half2_rn(f1.x + p.z, f1.y + p.w);
                val.x = *(uint32_t*)&r0; val.y = *(uint32_t*)&r1;
            }
        }
        *(uint2*)(As + row * LDA + c4 * 4) = val;
    }

    constexpr int BU4 = KPAD / 8;            // 24
    constexpr int NB = (64 * BU4) / 256;     // 6
    // preload tile 0
    for (int i = 0; i < NB; i++) {
        int idx = tid + i * 256;
        int n = idx / BU4, c = idx % BU4;
        *(uint4*)(Bs0 + n * LDA + c * 8) = *(const uint4*)(BT + (long)n * KPAD + c * 8);
    }
    for (int i = 0; i < 4; i++) {
        int idx = tid + i * 256;
        int row = idx >> 6, c = idx & 63;
        bias0[row * LDC + c] = bias[c];
    }
    __syncthreads();

    for (int t = 0; t < NTILES; t++) {
        __half* Bcur = (t & 1) ? Bs1 : Bs0;
        __half* Bnxt = (t & 1) ? Bs0 : Bs1;
        float* bcur = (t & 1) ? bias1 : bias0;
        float* bnxt = (t & 1) ? bias0 : bias1;
        int n0 = t * 64;
        bool has_next = (t + 1 < NTILES);

        uint4 breg[NB];
        float creg[4];
        if (has_next) {
            int n0n = n0 + 64;
#pragma unroll
            for (int i = 0; i < NB; i++) {
                int idx = tid + i * 256;
                int n = idx / BU4, c = idx % BU4;
                breg[i] = *(const uint4*)(BT + (long)(n0n + n) * KPAD + c * 8);
            }
#pragma unroll
            for (int i = 0; i < 4; i++) {
                int idx = tid + i * 256;
                int c = idx & 63;
                creg[i] = (n0n + c < C3) ? bias[n0n + c] : 0.f;
            }
        }

        wmma::fragment<wmma::accumulator, 16, 16, 16, float> acc[2][2];
#pragma unroll
        for (int i = 0; i < 2; i++)
#pragma unroll
            for (int j = 0; j < 2; j++)
                wmma::load_matrix_sync(acc[i][j], bcur + wn + j * 16, LDC, wmma::mem_row_major);
#pragma unroll
        for (int k = 0; k < KPAD; k += 16) {
            wmma::fragment<wmma::matrix_a, 16, 16, 16, __half, wmma::row_major> af[2];
            wmma::fragment<wmma::matrix_b, 16, 16, 16, __half, wmma::col_major> bf[2];
#pragma unroll
            for (int i = 0; i < 2; i++)
                wmma::load_matrix_sync(af[i], As + (wm + i * 16) * LDA + k, LDA);
#pragma unroll
            for (int j = 0; j < 2; j++)
                wmma::load_matrix_sync(bf[j], Bcur + (wn + j * 16) * LDA + k, LDA);
#pragma unroll
            for (int i = 0; i < 2; i++)
#pragma unroll
                for (int j = 0; j < 2; j++)
                    wmma::mma_sync(acc[i][j], af[i], bf[j], acc[i][j]);
        }
#pragma unroll
        for (int i = 0; i < 2; i++)
#pragma unroll
            for (int j = 0; j < 2; j++)
                wmma::store_matrix_sync(Cout + (long)(m0 + wm + i * 16) * QKV_STR + n0 + wn + j * 16,
                                        acc[i][j], QKV_STR, wmma::mem_row_major);
        if (has_next) {
#pragma unroll
            for (int i = 0; i < NB; i++) {
                int idx = tid + i * 256;
                int n = idx / BU4, c = idx % BU4;
                *(uint4*)(Bnxt + n * LDA + c * 8) = breg[i];
            }
#pragma unroll
            for (int i = 0; i < 4; i++) {
                int idx = tid + i * 256;
                int row = idx >> 6, c = idx & 63;
                bnxt[row * LDC + c] = creg[i];
            }
        }
        __syncthreads();
    }
}

// ---------------- proj GEMM: y_w = x[img] + xo_h @ Wp^T + bias; direct store (window order) ----
__global__ __launch_bounds__(256) void gemm_proj(const float* __restrict__ bias,
                                                 const float* __restrict__ x) {
    constexpr int KPAD = 384, LDA = 392, LDC = 68, NTILES = 3;
    extern __shared__ __align__(16) char smem[];
    __half* As = (__half*)smem;                      // [128][392]
    __half* Bs = As + 128 * LDA;                     // [64][392]
    float* resT = (float*)(Bs + 64 * LDA);           // [128][68]
    int* imgIdx = (int*)(resT + 128 * LDC);          // [128]

    int tid = threadIdx.x, wid = tid >> 5;
    int m0 = blockIdx.x * 128;
    int wm = (wid & 3) * 32, wn = (wid >> 2) * 32;

    if (tid < 128) imgIdx[tid] = row_to_img(m0 + tid);

    constexpr int KF4 = KPAD / 4;    // 96
    constexpr int KR4 = C2 / 4;      // 90
    for (int idx = tid; idx < 128 * KF4; idx += 256) {
        int row = idx / KF4, c4 = idx % KF4;
        uint2 val = make_uint2(0u, 0u);
        if (c4 < KR4)
            val = *(const uint2*)(g_xo_h + (long)(m0 + row) * C2 + c4 * 4);
        *(uint2*)(As + row * LDA + c4 * 4) = val;
    }

    constexpr int BU4 = KPAD / 8;    // 48
    for (int t = 0; t < NTILES; t++) {
        int n0 = t * 64;
        for (int idx = tid; idx < 64 * BU4; idx += 256) {
            int n = idx / BU4, c = idx % BU4;
            *(uint4*)(Bs + n * LDA + c * 8) = *(const uint4*)(g_wT_pr + (long)(n0 + n) * KPAD + c * 8);
        }
        for (int idx = tid; idx < 128 * 16; idx += 256) {
            int row = idx >> 4, c4 = (idx & 15) * 4;
            int n = n0 + c4;
            float4 v = make_float4(0.f, 0.f, 0.f, 0.f);
            if (n + 4 <= CC) {
                const float4 bv = *(const float4*)(bias + n);
                const float4 xr = *(const float4*)(x + (long)imgIdx[row] * CC + n);
                v.x = bv.x + xr.x; v.y = bv.y + xr.y; v.z = bv.z + xr.z; v.w = bv.w + xr.w;
            }
            *(float4*)(resT + row * LDC + c4) = v;
        }
        __syncthreads();

        wmma::fragment<wmma::accumulator, 16, 16, 16, float> acc[2][2];
#pragma unroll
        for (int i = 0; i < 2; i++)
#pragma unroll
            for (int j = 0; j < 2; j++)
                wmma::load_matrix_sync(acc[i][j], resT + (wm + i * 16) * LDC + wn + j * 16, LDC, wmma::mem_row_major);
#pragma unroll
        for (int k = 0; k < KPAD; k += 16) {
            wmma::fragment<wmma::matrix_a, 16, 16, 16, __half, wmma::row_major> af[2];
            wmma::fragment<wmma::matrix_b, 16, 16, 16, __half, wmma::col_major> bf[2];
#pragma unroll
            for (int i = 0; i < 2; i++)
                wmma::load_matrix_sync(af[i], As + (wm + i * 16) * LDA + k, LDA);
#pragma unroll
            for (int j = 0; j < 2; j++)
                wmma::load_matrix_sync(bf[j], Bs + (wn + j * 16) * LDA + k, LDA);
#pragma unroll
            for (int i = 0; i < 2; i++)
#pragma unroll
                for (int j = 0; j < 2; j++)
                    wmma::mma_sync(acc[i][j], af[i], bf[j], acc[i][j]);
        }
#pragma unroll
        for (int i = 0; i < 2; i++)
#pragma unroll
            for (int j = 0; j < 2; j++)
                wmma::store_matrix_sync(g_y + (long)(m0 + wm + i * 16) * Y_STR + n0 + wn + j * 16,
                                        acc[i][j], Y_STR, wmma::mem_row_major);
        __syncthreads();
    }
}

// ---------------- fused MLP GEMM: hid1_h = gelu(h2@W1+b1)*(h2@W2+b2), fp16 out ----------------
__global__ __launch_bounds__(256) void gemm_mlp(const float* __restrict__ bias1,
                                                const float* __restrict__ bias2) {
    constexpr int KPAD = 192, LDA = 200, LDC = 68, NTILES = 6;
    extern __shared__ __align__(16) char smem[];
    __half* As = (__half*)smem;
    __half* Bs = As + 128 * LDA;
    float* Cs = (float*)(Bs + 64 * LDA);
    float* Cs2 = Cs + 128 * LDC;
    float* biasS = Cs2 + 128 * LDC;

    int tid = threadIdx.x, wid = tid >> 5;
    int m0 = blockIdx.x * 128;
    int wm = (wid & 3) * 32, wn = (wid >> 2) * 32;

    constexpr int KF4 = KPAD / 4;
    constexpr int KR4 = CC / 4;
    for (int idx = tid; idx < 128 * KF4; idx += 256) {
        int row = idx / KF4, c4 = idx % KF4;
        uint2 val = make_uint2(0u, 0u);
        if (c4 < KR4)
            val = *(const uint2*)(g_h2_h + (long)(m0 + row) * CC + c4 * 4);
        *(uint2*)(As + row * LDA + c4 * 4) = val;
    }

    constexpr int BU4 = KPAD / 8;
    for (int t = 0; t < NTILES; t++) {
        int n0 = t * 64;
#pragma unroll
        for (int pass = 0; pass < 2; pass++) {
            const __half* Bp = (pass == 0) ? g_wT_f11 : g_wT_f12;
            const float* bp = (pass == 0) ? bias1 : bias2;
            float* Cdst = (pass == 0) ? Cs : Cs2;
            for (int idx = tid; idx < 16 * 64; idx += 256) {
                int row = idx >> 6, c = idx & 63;
                biasS[row * LDC + c] = (n0 + c < HID) ? bp[n0 + c] : 0.f;
            }
            for (int idx = tid; idx < 64 * BU4; idx += 256) {
                int n = idx / BU4, c = idx % BU4;
                *(uint4*)(Bs + n * LDA + c * 8) = *(const uint4*)(Bp + (long)(n0 + n) * KPAD + c * 8);
            }
            __syncthreads();
            wmma::fragment<wmma::accumulator, 16, 16, 16, float> acc[2][2];
#pragma unroll
            for (int i = 0; i < 2; i++)
#pragma unroll
                for (int j = 0; j < 2; j++)
                    wmma::load_matrix_sync(acc[i][j], biasS + wn + j * 16, LDC, wmma::mem_row_major);
#pragma unroll
            for (int k = 0; k < KPAD; k += 16) {
                wmma::fragment<wmma::matrix_a, 16, 16, 16, __half, wmma::row_major> af[2];
                wmma::fragment<wmma::matrix_b, 16, 16, 16, __half, wmma::col_major> bf[2];
#pragma unroll
                for (int i = 0; i < 2; i++)
                    wmma::load_matrix_sync(af[i], As + (wm + i * 16) * LDA + k, LDA);
#pragma unroll
                for (int j = 0; j < 2; j++)
                    wmma::load_matrix_sync(bf[j], Bs + (wn + j * 16) * LDA + k, LDA);
#pragma unroll
                for (int i = 0; i < 2; i++)
#pragma unroll
                    for (int j = 0; j < 2; j++)
                        wmma::mma_sync(acc[i][j], af[i], bf[j], acc[i][j]);
            }
#pragma unroll
            for (int i = 0; i < 2; i++)
#pragma unroll
                for (int j = 0; j < 2; j++)
                    wmma::store_matrix_sync(Cdst + (wm + i * 16) * LDC + wn + j * 16,
                                            acc[i][j], LDC, wmma::mem_row_major);
            __syncthreads();
        }
        for (int idx = tid; idx < 128 * 16; idx += 256) {
            int row = idx >> 4, c4 = (idx & 15) * 4;
            float4 v = *(float4*)(Cs + row * LDC + c4);
            float4 v2 = *(float4*)(Cs2 + row * LDC + c4);
            float4 o;
            o.x = 0.5f * v.x * (1.f + erff(v.x * 0.70710678f)) * v2.x;
            o.y = 0.5f * v.y * (1.f + erff(v.y * 0.70710678f)) * v2.y;
            o.z = 0.5f * v.z * (1.f + erff(v.z * 0.70710678f)) * v2.z;
            o.w = 0.5f * v.w * (1.f + erff(v.w * 0.70710678f)) * v2.w;
            __half2 a = __floats2half2_rn(o.x, o.y);
            __half2 b = __floats2half2_rn(o.z, o.w);
            *(uint2*)(g_hid1_h + (long)(m0 + row) * HID_STR + t * 64 + c4) =
                make_uint2(*(uint32_t*)&a, *(uint32_t*)&b);
        }
        __syncthreads();
    }
}

// ---------------- fc2 GEMM: out[img] = y_w + hid1_h @ Wf2^T + bias; scatter epilogue ----------------
__global__ __launch_bounds__(256) void gemm_fc2(const float* __restrict__ bias,
                                                float* __restrict__ out) {
    constexpr int KPAD = 384, LDA = 392, LDC = 68, NTILES = 3;
    extern __shared__ __align__(16) char smem[];
    __half* As = (__half*)smem;
    __half* Bs = As + 128 * LDA;
    float* resT = (float*)(Bs + 64 * LDA);
    float* Cs = resT + 128 * LDC;
    int* imgIdx = (int*)(Cs + 128 * LDC);

    int tid = threadIdx.x, wid = tid >> 5;
    int m0 = blockIdx.x * 128;
    int wm = (wid & 3) * 32, wn = (wid >> 2) * 32;

    if (tid < 128) imgIdx[tid] = row_to_img(m0 + tid);

    constexpr int KF4 = KPAD / 4;    // 96, full (hid pad cols are zero)
    for (int idx = tid; idx < 128 * KF4; idx += 256) {
        int row = idx / KF4, c4 = idx % KF4;
        *(uint2*)(As + row * LDA + c4 * 4) =
            *(const uint2*)(g_hid1_h + (long)(m0 + row) * HID_STR + c4 * 4);
    }

    constexpr int BU4 = KPAD / 8;
    for (int t = 0; t < NTILES; t++) {
        int n0 = t * 64;
        for (int idx = tid; idx < 64 * BU4; idx += 256) {
            int n = idx / BU4, c = idx % BU4;
            *(uint4*)(Bs + n * LDA + c * 8) = *(const uint4*)(g_wT_f2 + (long)(n0 + n) * KPAD + c * 8);
        }
        for (int idx = tid; idx < 128 * 16; idx += 256) {
            int row = idx >> 4, c4 = (idx & 15) * 4;
            int n = n0 + c4;
            float4 v = make_float4(0.f, 0.f, 0.f, 0.f);
            if (n + 4 <= CC) {
                const float4 bv = *(const float4*)(bias + n);
                const float4 yr = *(const float4*)(g_y + (long)(m0 + row) * Y_STR + n);
                v.x = bv.x + yr.x; v.y = bv.y + yr.y; v.z = bv.z + yr.z; v.w = bv.w + yr.w;
            }
            *(float4*)(resT + row * LDC + c4) = v;
        }
        __syncthreads();

        wmma::fragment<wmma::accumulator, 16, 16, 16, float> acc[2][2];
#pragma unroll
        for (int i = 0; i < 2; i++)
#pragma unroll
            for (int j = 0; j < 2; j++)
                wmma::load_matrix_sync(acc[i][j], resT + (wm + i * 16) * LDC + wn + j * 16, LDC, wmma::mem_row_major);
#pragma unroll
        for (int k = 0; k < KPAD; k += 16) {
            wmma::fragment<wmma::matrix_a, 16, 16, 16, __half, wmma::row_major> af[2];
            wmma::fragment<wmma::matrix_b, 16, 16, 16, __half, wmma::col_major> bf[2];
#pragma unroll
            for (int i = 0; i < 2; i++)
                wmma::load_matrix_sync(af[i], As + (wm + i * 16) * LDA + k, LDA);
#pragma unroll
            for (int j = 0; j < 2; j++)
                wmma::load_matrix_sync(bf[j], Bs + (wn + j * 16) * LDA + k, LDA);
#pragma unroll
            for (int i = 0; i < 2; i++)
#pragma unroll
                for (int j = 0; j < 2; j++)
                    wmma::mma_sync(acc[i][j], af[i], bf[j], acc[i][j]);
        }
#pragma unroll
        for (int i = 0; i < 2; i++)
#pragma unroll
            for (int j = 0; j < 2; j++)
                wmma::store_matrix_sync(Cs + (wm + i * 16) * LDC + wn + j * 16,
                                        acc[i][j], LDC, wmma::mem_row_major);
        __syncthreads();

        for (int idx = tid; idx < 128 * 16; idx += 256) {
            int row = idx >> 4, c4 = (idx & 15) * 4;
            int n = n0 + c4;
            if (n + 4 <= CC) {
                float4 v = *(float4*)(Cs + row * LDC + c4);
                *(float4*)(out + (long)imgIdx[row] * CC + n) = v;
            }
        }
        __syncthreads();
    }
}

// ---------------- self attention via wmma; P aliases S; fp16 out ----------------
#define LQ 40
#define LS 132
#define LO 36
__global__ __launch_bounds__(256) void self_attn_kernel(const float* __restrict__ mask) {
    int h = blockIdx.x, w = blockIdx.y;
    int tid = threadIdx.x, wid = tid >> 5, lane = tid & 31;
    extern __shared__ __align__(16) char smraw[];
    __half* Qs = (__half*)smraw;
    __half* Ks = Qs + 128 * LQ;
    __half* Vs = Ks + 128 * LQ;
    float* S = (float*)(Vs + 128 * LQ);
    __half* P = (__half*)S;
    float* rsum = (float*)(S + 128 * LS);
    float* Of = (float*)Qs;

    const float* base = g_qkvS + (long)w * NTOK * QKV_STR + h * HDIM;

    {
        int row = tid >> 1, part = tid & 1;
        const float* src = base + (long)row * QKV_STR;
        int d0 = part * 15;
#pragma unroll
        for (int dd = 0; dd < 15; dd++) {
            int d = d0 + dd;
            Qs[row * LQ + d] = __float2half(src[d] * ATT_SCALE);
            Ks[row * LQ + d] = __float2half(src[180 + d]);
            Vs[row * LQ + d] = __float2half(src[360 + d]);
        }
        if (part) {
            Qs[row * LQ + 30] = __float2half(0.f); Qs[row * LQ + 31] = __float2half(0.f);
            Ks[row * LQ + 30] = __float2half(0.f); Ks[row * LQ + 31] = __float2half(0.f);
            Vs[row * LQ + 30] = __float2half(0.f); Vs[row * LQ + 31] = __float2half(0.f);
        }
    }
    __syncthreads();

    {
        wmma::fragment<wmma::accumulator, 16, 16, 16, float> acc[8];
#pragma unroll
        for (int j = 0; j < 8; j++) wmma::fill_fragment(acc[j], 0.f);
#pragma unroll
        for (int k = 0; k < 2; k++) {
            wmma::fragment<wmma::matrix_a, 16, 16, 16, __half, wmma::row_major> af;
            wmma::load_matrix_sync(af, Qs + (wid * 16) * LQ + k * 16, LQ);
#pragma unroll
            for (int j = 0; j < 8; j++) {
                wmma::fragment<wmma::matrix_b, 16, 16, 16, __half, wmma::col_major> bf;
                wmma::load_matrix_sync(bf, Ks + (j * 16) * LQ + k * 16, LQ);
                wmma::mma_sync(acc[j], af, bf, acc[j]);
            }
        }
#pragma unroll
        for (int j = 0; j < 8; j++)
            wmma::store_matrix_sync(S + (wid * 16) * LS + j * 16, acc[j], LS, wmma::mem_row_major);
    }
    __syncthreads();

    {
        const float* bbase = g_bias6 + h * (NTOK * NTOK);
        const float* mbase = mask + (long)w * (NTOK * NTOK);
        for (int rr = 0; rr < 16; rr++) {
            int r = wid * 16 + rr;
            float4 s4 = *(float4*)(S + r * LS + lane * 4);
            float4 b4 = *(const float4*)(bbase + r * NTOK + lane * 4);
            float4 m4 = *(const float4*)(mbase + r * NTOK + lane * 4);
            float p0 = __expf(s4.x + b4.x + m4.x);
            float p1 = __expf(s4.y + b4.y + m4.y);
            float p2 = __expf(s4.z + b4.z + m4.z);
            float p3 = __expf(s4.w + b4.w + m4.w);
            __half2 h0 = __floats2half2_rn(p0, p1);
            __half2 h1 = __floats2half2_rn(p2, p3);
            uint2 pk = make_uint2(*(uint32_t*)&h0, *(uint32_t*)&h1);
            *(uint2*)(P + r * (2 * LS) + lane * 4) = pk;
            float psum = p0 + p1 + p2 + p3;
#pragma unroll
            for (int o = 16; o > 0; o >>= 1) psum += __shfl_xor_sync(0xffffffffu, psum, o);
            if (lane == 0) rsum[r] = 1.f / psum;
        }
    }
    __syncthreads();

    {
        wmma::fragment<wmma::accumulator, 16, 16, 16, float> acc[2];
        wmma::fill_fragment(acc[0], 0.f);
        wmma::fill_fragment(acc[1], 0.f);
#pragma unroll
        for (int k = 0; k < 8; k++) {
            wmma::fragment<wmma::matrix_a, 16, 16, 16, __half, wmma::row_major> pf;
            wmma::load_matrix_sync(pf, P + (wid * 16) * (2 * LS) + k * 16, 2 * LS);
#pragma unroll
            for (int j = 0; j < 2; j++) {
                wmma::fragment<wmma::matrix_b, 16, 16, 16, __half, wmma::row_major> vf;
                wmma::load_matrix_sync(vf, Vs + (k * 16) * LQ + j * 16, LQ);
                wmma::mma_sync(acc[j], pf, vf, acc[j]);
            }
        }
#pragma unroll
        for (int j = 0; j < 2; j++)
            wmma::store_matrix_sync(Of + (wid * 16) * LO + j * 16, acc[j], LO, wmma::mem_row_major);
    }
    __syncthreads();

    {
        int row = tid >> 1, part = tid & 1;
        float inv = rsum[row];
        __half* orow = g_xo_h + (long)(w * NTOK + row) * C2 + CC + h * HDIM;
        int d0 = part * 15;
#pragma unroll
        for (int dd = 0; dd < 15; dd++)
            orow[d0 + dd] = __float2half(Of[row * LO + d0 + dd] * inv);
    }
}

// ---------------- mutual attention via wmma; P aliases S; fp16 out ----------------
#define LSM 68
__global__ __launch_bounds__(256) void mut_attn_kernel(const float* __restrict__ mask) {
    int h = blockIdx.x, w = blockIdx.y;
    int tid = threadIdx.x, wid = tid >> 5, lane = tid & 31;
    extern __shared__ __align__(16) char smraw[];
    __half* Qs = (__half*)smraw;
    __half* Ks = Qs + 128 * LQ;
    __half* Vs = Ks + 128 * LQ;
    float* S = (float*)(Vs + 128 * LQ);
    __half* P = (__half*)S;
    float* rsum = (float*)(S + 2 * 64 * LSM);
    float* Of = (float*)Qs;

    const float* base = g_qkvM + (long)w * NTOK * QKV_STR + h * HDIM;

    {
        int row = tid >> 1, part = tid & 1;
        int qt = (row < 64) ? (64 + row) : (row - 64);
        const float* qsrc = base + (long)qt * QKV_STR;
        const float* ksrc = base + (long)row * QKV_STR;
        int d0 = part * 15;
#pragma unroll
        for (int dd = 0; dd < 15; dd++) {
            int d = d0 + dd;
            Qs[row * LQ + d] = __float2half(qsrc[d] * ATT_SCALE);
            Ks[row * LQ + d] = __float2half(ksrc[180 + d]);
            Vs[row * LQ + d] = __float2half(ksrc[360 + d]);
        }
        if (part) {
            Qs[row * LQ + 30] = __float2half(0.f); Qs[row * LQ + 31] = __float2half(0.f);
            Ks[row * LQ + 30] = __float2half(0.f); Ks[row * LQ + 31] = __float2half(0.f);
            Vs[row * LQ + 30] = __float2half(0.f); Vs[row * LQ + 31] = __float2half(0.f);
        }
    }
    __syncthreads();

    int g = wid >> 2, mt = wid & 3;

    {
        wmma::fragment<wmma::accumulator, 16, 16, 16, float> acc[4];
#pragma unroll
        for (int j = 0; j < 4; j++) wmma::fill_fragment(acc[j], 0.f);
#pragma unroll
        for (int k = 0; k < 2; k++) {
            wmma::fragment<wmma::matrix_a, 16, 16, 16, __half, wmma::row_major> af;
            wmma::load_matrix_sync(af, Qs + (g * 64 + mt * 16) * LQ + k * 16, LQ);
#pragma unroll
            for (int j = 0; j < 4; j++) {
                wmma::fragment<wmma::matrix_b, 16, 16, 16, __half, wmma::col_major> bf;
                wmma::load_matrix_sync(bf, Ks + (g * 64 + j * 16) * LQ + k * 16, LQ);
                wmma::mma_sync(acc[j], af, bf, acc[j]);
            }
        }
#pragma unroll
        for (int j = 0; j < 4; j++)
            wmma::store_matrix_sync(S + g * 64 * LSM + (mt * 16) * LSM + j * 16, acc[j], LSM, wmma::mem_row_major);
    }
    __syncthreads();

    {
        const float* mbase = mask + (long)w * (NTOK * NTOK);
        for (int rr = 0; rr < 16; rr++) {
            int r = wid * 16 + rr;
            int gg = r >> 6, i = r & 63;
            float2 s2 = *(float2*)(S + gg * 64 * LSM + i * LSM + lane * 2);
            float2 m2 = *(const float2*)(mbase + i * NTOK + lane * 2);
            float p0 = __expf(s2.x + m2.x);
            float p1 = __expf(s2.y + m2.y);
            __half2 hp = __floats2half2_rn(p0, p1);
            *(uint32_t*)(P + gg * 64 * (2 * LSM) + i * (2 * LSM) + lane * 2) = *(uint32_t*)&hp;
            float psum = p0 + p1;
#pragma unroll
            for (int o = 16; o > 0; o >>= 1) psum += __shfl_xor_sync(0xffffffffu, psum, o);
            if (lane == 0) rsum[r] = 1.f / psum;
        }
    }
    __syncthreads();

    {
        wmma::fragment<wmma::accumulator, 16, 16, 16, float> acc[2];
        wmma::fill_fragment(acc[0], 0.f);
        wmma::fill_fragment(acc[1], 0.f);
#pragma unroll
        for (int k = 0; k < 4; k++) {
            wmma::fragment<wmma::matrix_a, 16, 16, 16, __half, wmma::row_major> pf;
            wmma::load_matrix_sync(pf, P + g * 64 * (2 * LSM) + (mt * 16) * (2 * LSM) + k * 16, 2 * LSM);
#pragma unroll
            for (int j = 0; j < 2; j++) {
                wmma::fragment<wmma::matrix_b, 16, 16, 16, __half, wmma::row_major> vf;
                wmma::load_matrix_sync(vf, Vs + (g * 64 + k * 16) * LQ + j * 16, LQ);
                wmma::mma_sync(acc[j], pf, vf, acc[j]);
            }
        }
#pragma unroll
        for (int j = 0; j < 2; j++)
            wmma::store_matrix_sync(Of + (g * 64 + mt * 16) * LO + j * 16, acc[j], LO, wmma::mem_row_major);
    }
    __syncthreads();

    {
        int row = tid >> 1, part = tid & 1;
        float inv = rsum[row];
        __half* orow = g_xo_h + (long)(w * NTOK + row) * C2 + h * HDIM;
        int d0 = part * 15;
#pragma unroll
        for (int dd = 0; dd < 15; dd++)
            orow[d0 + dd] = __float2half(Of[row * LO + d0 + dd] * inv);
    }
}

// ---------------- launcher ----------------
extern "C" void kernel_launch(void* const* d_in, const int* in_sizes, int n_in,
                              void* d_out, int out_size) {
    const float* x     = (const float*)d_in[0];
    const float* mask  = (const float*)d_in[1];
    const float* g1    = (const float*)d_in[2];
    const float* b1    = (const float*)d_in[3];
    const float* g2    = (const float*)d_in[4];
    const float* b2    = (const float*)d_in[5];
    const float* wqs   = (const float*)d_in[6];
    const float* bqs   = (const float*)d_in[7];
    const float* wqm   = (const float*)d_in[8];
    const float* bqm   = (const float*)d_in[9];
    const float* rpb   = (const float*)d_in[10];
    const float* posb  = (const float*)d_in[11];
    const float* wproj = (const float*)d_in[12];
    const float* bproj = (const float*)d_in[13];
    const float* w11   = (const float*)d_in[14];
    const float* b11   = (const float*)d_in[15];
    const float* w12   = (const float*)d_in[16];
    const float* b12   = (const float*)d_in[17];
    const float* w2    = (const float*)d_in[18];
    const float* b2f   = (const float*)d_in[19];
    const int*   rpi   = (const int*)d_in[20];
    float* out = (float*)d_out;

    const int SMEM_QKV  = 128 * 200 * 2 + 2 * 64 * 200 * 2 + 2 * 16 * 68 * 4;            // 111104
    const int SMEM_PROJ = 128 * 392 * 2 + 64 * 392 * 2 + 128 * 68 * 4 + 128 * 4;         // 185856
    const int SMEM_MLP  = 128 * 200 * 2 + 64 * 200 * 2 + 2 * 128 * 68 * 4 + 16 * 68 * 4; // 150784
    const int SMEM_FC2  = 128 * 392 * 2 + 64 * 392 * 2 + 2 * 128 * 68 * 4 + 128 * 4;     // 220672
    const int SMEM_SELF = 3 * 128 * LQ * 2 + 128 * LS * 4 + 128 * 4;                     // 98816
    const int SMEM_MUT  = 3 * 128 * LQ * 2 + 2 * 64 * LSM * 4 + 128 * 4;                 // 66048

    cudaFuncSetAttribute(&gemm_qkv<0, 0, 0>, cudaFuncAttributeMaxDynamicSharedMemorySize, SMEM_QKV);
    cudaFuncSetAttribute(&gemm_qkv<1, 1, 1>, cudaFuncAttributeMaxDynamicSharedMemorySize, SMEM_QKV);
    cudaFuncSetAttribute(gemm_proj, cudaFuncAttributeMaxDynamicSharedMemorySize, SMEM_PROJ);
    cudaFuncSetAttribute(gemm_mlp,  cudaFuncAttributeMaxDynamicSharedMemorySize, SMEM_MLP);
    cudaFuncSetAttribute(gemm_fc2,  cudaFuncAttributeMaxDynamicSharedMemorySize, SMEM_FC2);
    cudaFuncSetAttribute(self_attn_kernel, cudaFuncAttributeMaxDynamicSharedMemorySize, SMEM_SELF);
    cudaFuncSetAttribute(mut_attn_kernel,  cudaFuncAttributeMaxDynamicSharedMemorySize, SMEM_MUT);

    prep_qkv_kernel<<<(2 * 576 * 192 + 255) / 256, 256>>>(wqs, wqm);            // 0
    ln_kernel<0><<<(M_ROWS * 32) / 256, 256>>>(x, g1, b1);                      // 1
    prep_rest_kernel<<<(4 * 192 * 384 + 255) / 256, 256>>>(wproj, w11, w12, w2);// 2
    gemm_qkv<0, 0, 0><<<768, 256, SMEM_QKV>>>(bqs, nullptr);                    // 3 <- ncu slot
    gemm_qkv<1, 1, 1><<<768, 256, SMEM_QKV>>>(bqm, posb);                       // 4
    bias_kernel<<<(NHD * NTOK * NTOK + 255) / 256, 256>>>(rpb, rpi);            // 5
    dim3 ga(NHD, NWIN);
    self_attn_kernel<<<ga, 256, SMEM_SELF>>>(mask);                             // 6
    mut_attn_kernel<<<ga, 256, SMEM_MUT>>>(mask);                               // 7
    gemm_proj<<<768, 256, SMEM_PROJ>>>(bproj, x);                               // 8
    ln_kernel<1><<<(M_ROWS * 32) / 256, 256>>>(nullptr, g2, b2);                // 9
    gemm_mlp<<<768, 256, SMEM_MLP>>>(b11, b12);                                 // 10
    gemm_fc2<<<768, 256, SMEM_FC2>>>(b2f, out);                                 // 11
}